// round 13
// baseline (speedup 1.0000x reference)
#include <cuda_runtime.h>
#include <cuda_fp16.h>
#include <math.h>

// Problem constants
#define BTOT   1792          // N*D*H = 1*32*56
#define CH_STR 7168          // 128*56
#define XPLANE 100352        // 32*56*56 == BTOT*56
#define NQKV   100352.0
#define NSIM   5619712.0     // BTOT*56*56
#define EPSBN  1e-5f

typedef unsigned long long u64t;

// ---- packed fp32x2 helpers (sm_103a dual-fp32; lanewise IEEE fp32) ---------
__device__ __forceinline__ u64t pack2(float lo, float hi) {
    u64t d; asm("mov.b64 %0, {%1, %2};" : "=l"(d) : "f"(lo), "f"(hi)); return d;
}
__device__ __forceinline__ float2 unpack2(u64t d) {
    float2 r; asm("mov.b64 {%0, %1}, %2;" : "=f"(r.x), "=f"(r.y) : "l"(d)); return r;
}
__device__ __forceinline__ u64t ffma2(u64t a, u64t b, u64t c) {
    u64t d; asm("fma.rn.f32x2 %0, %1, %2, %3;" : "=l"(d) : "l"(a), "l"(b), "l"(c));
    return d;
}

// ---------------- scratch (device globals; no runtime alloc) ----------------
__device__ float  g_qkv[BTOT * 128 * 56];  // [b][o][i]  o = g*16+cc
__device__ __half g_so [BTOT * 128 * 56];  // [b][o2][i] fp16 (stats kept fp32)
__device__ float  g_wT[64][128];           // transposed qkv weights [c][o]
__device__ double g_qsum[128], g_qsq[128];
__device__ double g_ssum[24],  g_ssq[24];
__device__ double g_osum[128], g_osq[128];
__device__ float g_SR[8][56];
__device__ float g_TQ[10][56];
__device__ float g_TK[10][56];

__constant__ int   c_PA[10] = {0,0,0,0,1,1,1,2,2,3};
__constant__ int   c_PB[10] = {0,1,2,3,1,2,3,2,3,3};
__constant__ float c_PW[10] = {1.f,2.f,2.f,2.f,1.f,2.f,2.f,1.f,2.f,1.f};

// ---------------- K_init: zero accumulators + prefix tables + w transpose ---
__global__ void k_init(const float* __restrict__ relative,
                       const float* __restrict__ w) {
    __shared__ float rel[8][112];
    int t = threadIdx.x;
    if (t < 128) { g_qsum[t] = 0.0; g_qsq[t] = 0.0; g_osum[t] = 0.0; g_osq[t] = 0.0; }
    if (t < 24)  { g_ssum[t] = 0.0; g_ssq[t] = 0.0; }
    for (int idx = t; idx < 128 * 64; idx += 256) {
        int o = idx >> 6, c = idx & 63;
        g_wT[c][o] = w[idx];
    }
    for (int idx = t; idx < 8 * 111; idx += 256)
        rel[idx / 111][idx % 111] = relative[idx];
    __syncthreads();
    for (int task = t; task < 448; task += 256) {
        int c = task / 56, i = task % 56;
        float s = 0.f;
        for (int d = 0; d < 56; ++d) s += rel[c][i + d];
        g_SR[c][i] = s;
    }
    for (int task = t; task < 1120; task += 256) {
        int p = task / 56, i = task % 56;
        int pp = p % 10; int isK = (p >= 10) ? 4 : 0;
        int a = c_PA[pp] + isK, bb = c_PB[pp] + isK;
        float s = 0.f;
        for (int d = 0; d < 56; ++d) s += rel[a][i + d] * rel[bb][i + d];
        s *= c_PW[pp];
        if (isK) g_TK[pp][i] = s; else g_TQ[pp][i] = s;
    }
}

// ---------------- K1: qkv = w @ x  — high-occupancy f32x2 -------------------
// 256 threads: og = t>>3 (4 channels), ig = t&7 (7 positions).
// Weights from L2-resident g_wT (no smem tile); x staged as (x,x) u64 pairs.
__global__ void __launch_bounds__(256, 5) k_qkv(const float* __restrict__ x) {
    __shared__ __align__(16) u64t xs2[64][60];   // (x,x) pairs, 8B banks, conflict-free
    const int b = blockIdx.x;
    const int t = threadIdx.x;

    for (int idx = t; idx < 64 * 14; idx += 256) {
        int c = idx / 14, q4 = idx % 14;
        float4 v = *(const float4*)&x[c * XPLANE + b * 56 + q4 * 4];
        xs2[c][q4 * 4 + 0] = pack2(v.x, v.x);
        xs2[c][q4 * 4 + 1] = pack2(v.y, v.y);
        xs2[c][q4 * 4 + 2] = pack2(v.z, v.z);
        xs2[c][q4 * 4 + 3] = pack2(v.w, v.w);
    }
    __syncthreads();

    const int og = t >> 3;                 // 0..31  (4 output channels each)
    const int ig = t & 7;                  // 0..7   (7 positions each)
    const int o0 = og * 4, i0 = ig * 7;
    u64t acc2[2][7];
#pragma unroll
    for (int p = 0; p < 2; ++p)
#pragma unroll
        for (int ii = 0; ii < 7; ++ii) acc2[p][ii] = 0ull;

#pragma unroll 4
    for (int c = 0; c < 64; ++c) {
        u64t w01 = *(const u64t*)&g_wT[c][o0];
        u64t w23 = *(const u64t*)&g_wT[c][o0 + 2];
#pragma unroll
        for (int ii = 0; ii < 7; ++ii) {
            u64t xx = xs2[c][i0 + ii];
            acc2[0][ii] = ffma2(w01, xx, acc2[0][ii]);
            acc2[1][ii] = ffma2(w23, xx, acc2[1][ii]);
        }
    }
    float* outb = g_qkv + (size_t)b * CH_STR;
#pragma unroll
    for (int p = 0; p < 2; ++p) {
        float s0 = 0.f, sq0 = 0.f, s1 = 0.f, sq1 = 0.f;
#pragma unroll
        for (int ii = 0; ii < 7; ++ii) {
            float2 u = unpack2(acc2[p][ii]);
            outb[(o0 + 2 * p) * 56 + i0 + ii]     = u.x;
            outb[(o0 + 2 * p + 1) * 56 + i0 + ii] = u.y;
            s0 += u.x; sq0 += u.x * u.x;
            s1 += u.y; sq1 += u.y * u.y;
        }
        for (int off = 4; off; off >>= 1) {
            s0  += __shfl_down_sync(0xffffffffu, s0,  off);
            sq0 += __shfl_down_sync(0xffffffffu, sq0, off);
            s1  += __shfl_down_sync(0xffffffffu, s1,  off);
            sq1 += __shfl_down_sync(0xffffffffu, sq1, off);
        }
        if (ig == 0) {
            atomicAdd(&g_qsum[o0 + 2 * p],     (double)s0);
            atomicAdd(&g_qsq [o0 + 2 * p],     (double)sq0);
            atomicAdd(&g_qsum[o0 + 2 * p + 1], (double)s1);
            atomicAdd(&g_qsq [o0 + 2 * p + 1], (double)sq1);
        }
    }
}

// ---------------- K2: analytic sim moments (folds qkv-BN finalize) ----------
__global__ void __launch_bounds__(256) k_mom(const float* __restrict__ qg,
                                             const float* __restrict__ qb) {
    __shared__ float sQs[128], sQo[128];
    const int b = blockIdx.x;
    {
        int o = threadIdx.x;
        if (o < 128) {
            double inv = 1.0 / NQKV;
            double m = g_qsum[o] * inv;
            double v = g_qsq[o] * inv - m * m;
            float sc = qg[o] * rsqrtf((float)v + EPSBN);
            sQs[o] = sc;
            sQo[o] = qb[o] - (float)m * sc;
        }
    }
    __syncthreads();

    const int g = threadIdx.x >> 5;
    const int lane = threadIdx.x & 31;
    const float* base = g_qkv + (size_t)b * CH_STR + g * 16 * 56;

    float part[32];
#pragma unroll
    for (int v = 0; v < 32; ++v) part[v] = 0.f;

#pragma unroll
    for (int ii = 0; ii < 2; ++ii) {
        int i = lane + ii * 32;
        if (i < 56) {
            float q[4], k[4];
#pragma unroll
            for (int c = 0; c < 4; ++c) {
                int oq = g * 16 + c, ok = g * 16 + 4 + c;
                q[c] = base[c * 56 + i]       * sQs[oq] + sQo[oq];
                k[c] = base[(4 + c) * 56 + i] * sQs[ok] + sQo[ok];
            }
#pragma unroll
            for (int c = 0; c < 4; ++c) {
                part[c]     += q[c];
                part[4 + c] += k[c];
                part[28] += q[c] * g_SR[c][i];
                part[30] += k[c] * g_SR[4 + c][i];
            }
#pragma unroll
            for (int p = 0; p < 10; ++p) {
                float pq = q[c_PA[p]] * q[c_PB[p]];
                float pk = k[c_PA[p]] * k[c_PB[p]];
                part[8 + p]  += pq;
                part[18 + p] += pk;
                part[29] += pq * g_TQ[p][i];
                part[31] += pk * g_TK[p][i];
            }
        }
    }
#pragma unroll
    for (int v = 0; v < 32; ++v)
        for (int off = 16; off; off >>= 1)
            part[v] += __shfl_down_sync(0xffffffffu, part[v], off);

    if (lane == 0) {
        float S1 = 0.f, S2 = 0.f;
#pragma unroll
        for (int c = 0; c < 4; ++c) S1 += part[c] * part[4 + c];
#pragma unroll
        for (int p = 0; p < 10; ++p) S2 += c_PW[p] * part[8 + p] * part[18 + p];
        atomicAdd(&g_ssum[g],      (double)S1);
        atomicAdd(&g_ssq [g],      (double)S2);
        atomicAdd(&g_ssum[8 + g],  (double)(0.1f  * part[28]));
        atomicAdd(&g_ssq [8 + g],  (double)(0.01f * part[29]));
        atomicAdd(&g_ssum[16 + g], (double)(0.1f  * part[30]));
        atomicAdd(&g_ssq [16 + g], (double)(0.01f * part[31]));
    }
}

// ---- warp reduce-scatter: 16 partials spread over 8 consecutive lanes ------
__device__ __forceinline__ void reduce_scatter16(const float* av, int tj,
                                                 float& o0, float& o1) {
    float a8[8];
#pragma unroll
    for (int v = 0; v < 8; ++v) {
        float snd = (tj & 1) ? av[v] : av[8 + v];
        float kp  = (tj & 1) ? av[8 + v] : av[v];
        a8[v] = kp + __shfl_xor_sync(0xffffffffu, snd, 1);
    }
    float a4[4];
#pragma unroll
    for (int v = 0; v < 4; ++v) {
        float snd = (tj & 2) ? a8[v] : a8[4 + v];
        float kp  = (tj & 2) ? a8[4 + v] : a8[v];
        a4[v] = kp + __shfl_xor_sync(0xffffffffu, snd, 2);
    }
    float a2[2];
#pragma unroll
    for (int v = 0; v < 2; ++v) {
        float snd = (tj & 4) ? a4[v] : a4[2 + v];
        float kp  = (tj & 4) ? a4[2 + v] : a4[v];
        a2[v] = kp + __shfl_xor_sync(0xffffffffu, snd, 4);
    }
    o0 = a2[0]; o1 = a2[1];
}

// ---------------- K3: attention — grid 3584 = (b, head-half), 4 heads -------
__global__ void __launch_bounds__(224, 5) k_attn(const float* __restrict__ relative,
                                                 const float* __restrict__ qg,
                                                 const float* __restrict__ qb,
                                                 const float* __restrict__ sg,
                                                 const float* __restrict__ sb) {
    __shared__ __align__(16) float qsT[4][56][4];
    __shared__ __align__(16) float ksT[4][56][4];
    __shared__ __align__(16) float vsT[4][56][12];   // 48B stride, conflict-free
    __shared__ __align__(16) __half relQK[111][8];   // {relq[0..3][d], relk[0..3][110-d]}
    __shared__ __align__(16) __half relV[111][8];    // {relv[0..7][d]}
    __shared__ __align__(16) float SB[16][60];
    __shared__ float sQs[64], sQo[64], sC[16];

    const int b = blockIdx.x >> 1;
    const int half = blockIdx.x & 1;
    const int gbase = half * 4;
    const int t = threadIdx.x;

    if (t < 64) {
        int o = half * 64 + t;
        double inv = 1.0 / NQKV;
        double m = g_qsum[o] * inv;
        double v = g_qsq[o] * inv - m * m;
        float sc = qg[o] * rsqrtf((float)v + EPSBN);
        sQs[t] = sc;
        sQo[t] = qb[o] - (float)m * sc;
    } else if (t < 68) {
        int gl = t - 64;
        int g = gbase + gl;
        double inv = 1.0 / NSIM;
        float fac[3] = {1.f, 0.1f, 0.1f};
        float csum = 0.f;
        for (int r = 0; r < 3; ++r) {
            int idx = r * 8 + g;
            double m = g_ssum[idx] * inv;
            double v = g_ssq[idx] * inv - m * m;
            float aa = sg[idx] * rsqrtf((float)v + EPSBN);
            sC[4 * gl + r] = aa * fac[r];
            csum += sb[idx] - (float)m * aa;
        }
        sC[4 * gl + 3] = csum;
    }
    for (int idx = t; idx < 8 * 111; idx += 224) {
        int c = idx / 111, d = idx % 111;
        if (c < 4) relQK[d][c] = __float2half(relative[c * 111 + d]);
        else       relQK[d][c] = __float2half(relative[c * 111 + (110 - d)]);
    }
    for (int idx = t; idx < 8 * 111; idx += 224) {
        int c = idx / 111, d = idx % 111;
        relV[d][c] = __float2half(relative[(8 + c) * 111 + d]);
    }
    __syncthreads();

    {
        const float* src = g_qkv + (size_t)b * CH_STR + half * 64 * 56;
        const int chr = t / 14, i4 = t % 14;
#pragma unroll
        for (int it = 0; it < 4; ++it) {
            int ch = it * 16 + chr;
            float4 v = *(const float4*)&src[ch * 56 + i4 * 4];
            float sc = sQs[ch], of = sQo[ch];
            float vals[4] = {v.x * sc + of, v.y * sc + of, v.z * sc + of, v.w * sc + of};
            int gl = it, cc = chr;
#pragma unroll
            for (int e = 0; e < 4; ++e) {
                int i = i4 * 4 + e;
                if (cc < 4) qsT[gl][i][cc] = vals[e];
                else if (cc < 8) ksT[gl][i][cc - 4] = vals[e];
                else vsT[gl][i][cc - 8] = vals[e];
            }
        }
    }
    __syncthreads();

    const int lane = t & 31;
    const int tj = lane & 7, ig = lane >> 3;
    const int ti = (t >> 5) * 4 + ig;
    const int i0 = ti * 2, j0 = tj * 7;
    const int dbase = i0 - j0 + 49;
    const int chown = ((tj & 1) << 2) | (tj & 2) | ((tj >> 2) & 1);
    const int row_w = t / 14, c4_w = t % 14;

#pragma unroll 1
    for (int gl = 0; gl < 4; ++gl) {
        const int g = gbase + gl;
        const float cqk = sC[4 * gl], cqr = sC[4 * gl + 1], ckr = sC[4 * gl + 2], soff = sC[4 * gl + 3];

        float4 q0v = *(const float4*)qsT[gl][i0];
        float4 q1v = *(const float4*)qsT[gl][i0 + 1];

        float P[14];
        {
            float4 kcur, kprev;
#pragma unroll
            for (int cc = 0; cc < 8; ++cc) {
                int d = dbase + cc;
                uint4 rw = *(const uint4*)relQK[d];
                const __half2* hp = (const __half2*)&rw;
                float2 ra = __half22float2(hp[0]);
                float2 rb = __half22float2(hp[1]);
                float2 rc = __half22float2(hp[2]);
                float2 rd = __half22float2(hp[3]);
                if (cc <= 6) {
                    kcur = *(const float4*)ksT[gl][j0 + 6 - cc];
                    float qk = q0v.x * kcur.x + q0v.y * kcur.y + q0v.z * kcur.z + q0v.w * kcur.w;
                    float qr = q0v.x * ra.x + q0v.y * ra.y + q0v.z * rb.x + q0v.w * rb.y;
                    float kr = kcur.x * rc.x + kcur.y * rc.y + kcur.z * rd.x + kcur.w * rd.y;
                    P[6 - cc] = fmaf(cqk, qk, fmaf(cqr, qr, fmaf(ckr, kr, soff)));
                }
                if (cc >= 1) {
                    float qk = q1v.x * kprev.x + q1v.y * kprev.y + q1v.z * kprev.z + q1v.w * kprev.w;
                    float qr = q1v.x * ra.x + q1v.y * ra.y + q1v.z * rb.x + q1v.w * rb.y;
                    float kr = kprev.x * rc.x + kprev.y * rc.y + kprev.z * rd.x + kprev.w * rd.y;
                    P[7 + 7 - cc] = fmaf(cqk, qk, fmaf(cqr, qr, fmaf(ckr, kr, soff)));
                }
                kprev = kcur;
            }
        }

        float rinv0, rinv1;
        {
            float rs0 = 0.f, rs1 = 0.f;
#pragma unroll
            for (int jj = 0; jj < 7; ++jj) {
                float p0 = __expf(P[jj]);
                float p1 = __expf(P[7 + jj]);
                P[jj] = p0; P[7 + jj] = p1;
                rs0 += p0; rs1 += p1;
            }
#pragma unroll
            for (int m = 1; m < 8; m <<= 1) {
                rs0 += __shfl_xor_sync(0xffffffffu, rs0, m);
                rs1 += __shfl_xor_sync(0xffffffffu, rs1, m);
            }
            rinv0 = 1.0f / rs0;
            rinv1 = 1.0f / rs1;
        }

        {
            u64t av2[8];
#pragma unroll
            for (int v = 0; v < 8; ++v) av2[v] = 0ull;
#pragma unroll
            for (int jj = 0; jj < 7; ++jj) {
                const float* vr = &vsT[gl][j0 + jj][0];
                u64t v01 = *(const u64t*)&vr[0];
                u64t v23 = *(const u64t*)&vr[2];
                u64t v45 = *(const u64t*)&vr[4];
                u64t v67 = *(const u64t*)&vr[6];
                u64t pp0 = pack2(P[jj], P[jj]);
                u64t pp1 = pack2(P[7 + jj], P[7 + jj]);
                av2[0] = ffma2(pp0, v01, av2[0]);
                av2[1] = ffma2(pp1, v01, av2[1]);
                av2[2] = ffma2(pp0, v23, av2[2]);
                av2[3] = ffma2(pp1, v23, av2[3]);
                av2[4] = ffma2(pp0, v45, av2[4]);
                av2[5] = ffma2(pp1, v45, av2[5]);
                av2[6] = ffma2(pp0, v67, av2[6]);
                av2[7] = ffma2(pp1, v67, av2[7]);
            }
            float av[16];
#pragma unroll
            for (int cp = 0; cp < 4; ++cp) {
#pragma unroll
                for (int r = 0; r < 2; ++r) {
                    float2 u = unpack2(av2[cp * 2 + r]);
                    av[2 * (2 * cp) + r]     = u.x;
                    av[2 * (2 * cp + 1) + r] = u.y;
                }
            }
            float s0, s1;
            reduce_scatter16(av, tj, s0, s1);
            SB[2 * chown][i0]     = s0 * rinv0;
            SB[2 * chown][i0 + 1] = s1 * rinv1;
        }

        {
            float av[16];
#pragma unroll
            for (int v = 0; v < 16; ++v) av[v] = 0.f;
#pragma unroll
            for (int cc = 0; cc < 8; ++cc) {
                int d = dbase + cc;
                uint4 rw = *(const uint4*)relV[d];
                const __half2* hp = (const __half2*)&rw;
                float2 va = __half22float2(hp[0]);
                float2 vb = __half22float2(hp[1]);
                float2 vc = __half22float2(hp[2]);
                float2 vd = __half22float2(hp[3]);
                if (cc <= 6) {
                    float p = P[6 - cc];
                    av[0] += p * va.x; av[2]  += p * va.y; av[4]  += p * vb.x; av[6]  += p * vb.y;
                    av[8] += p * vc.x; av[10] += p * vc.y; av[12] += p * vd.x; av[14] += p * vd.y;
                }
                if (cc >= 1) {
                    float p = P[7 + 7 - cc];
                    av[1] += p * va.x; av[3]  += p * va.y; av[5]  += p * vb.x; av[7]  += p * vb.y;
                    av[9] += p * vc.x; av[11] += p * vc.y; av[13] += p * vd.x; av[15] += p * vd.y;
                }
            }
            float s0, s1;
            reduce_scatter16(av, tj, s0, s1);
            SB[2 * chown + 1][i0]     = s0 * rinv0 * 0.1f;
            SB[2 * chown + 1][i0 + 1] = s1 * rinv1 * 0.1f;
        }
        __syncthreads();

        {
            float4 v4 = *(const float4*)&SB[row_w][c4_w * 4];
            __half2 h0 = __floats2half2_rn(v4.x, v4.y);
            __half2 h1 = __floats2half2_rn(v4.z, v4.w);
            __half* ob = g_so + (size_t)b * CH_STR + g * 16 * 56 + row_w * 56 + c4_w * 4;
            uint2 st;
            st.x = *(unsigned*)&h0;
            st.y = *(unsigned*)&h1;
            *(uint2*)ob = st;
        }

        if (t < 128) {
            int row = t >> 3, sub = t & 7;
            float s1 = 0.f, s2 = 0.f;
#pragma unroll
            for (int e = 0; e < 7; ++e) {
                float v = SB[row][sub * 7 + e];
                s1 += v; s2 += v * v;
            }
#pragma unroll
            for (int m = 1; m < 8; m <<= 1) {
                s1 += __shfl_xor_sync(0xffffffffu, s1, m);
                s2 += __shfl_xor_sync(0xffffffffu, s2, m);
            }
            if (sub == 0) {
                atomicAdd(&g_osum[g * 16 + row], (double)s1);
                atomicAdd(&g_osq [g * 16 + row], (double)s2);
            }
        }
        __syncthreads();
    }
}

// ---------------- K4: out BN (folded finalize) + pair-sum + layout ----------
__global__ void __launch_bounds__(256) k_out(float* __restrict__ out,
                                             const float* __restrict__ og,
                                             const float* __restrict__ ob) {
    __shared__ float sOs[128], sOo[128];
    {
        int o = threadIdx.x;
        if (o < 128) {
            double inv = 1.0 / NQKV;
            double m = g_osum[o] * inv;
            double v = g_osq[o] * inv - m * m;
            float sc = og[o] * rsqrtf((float)v + EPSBN);
            sOs[o] = sc;
            sOo[o] = ob[o] - (float)m * sc;
        }
    }
    __syncthreads();
    int idx = blockIdx.x * 256 + threadIdx.x;
    if (idx >= 1605632) return;
    int e  = idx * 4;
    int cp = e / XPLANE;
    int r  = e % XPLANE;
    int bq = r / 56, i = r % 56;
    const __half* base = g_so + (size_t)bq * CH_STR + (2 * cp) * 56 + i;
    uint2 a = *(const uint2*)base;
    uint2 bb = *(const uint2*)(base + 56);
    __half2 ha0, ha1, hb0, hb1;
    *(unsigned*)&ha0 = a.x;  *(unsigned*)&ha1 = a.y;
    *(unsigned*)&hb0 = bb.x; *(unsigned*)&hb1 = bb.y;
    float2 s0a = __half22float2(ha0), s0b = __half22float2(ha1);
    float2 s1a = __half22float2(hb0), s1b = __half22float2(hb1);
    float sc0 = sOs[2 * cp], of0 = sOo[2 * cp];
    float sc1 = sOs[2 * cp + 1], of1 = sOo[2 * cp + 1];
    float4 o4;
    o4.x = s0a.x * sc0 + of0 + s1a.x * sc1 + of1;
    o4.y = s0a.y * sc0 + of0 + s1a.y * sc1 + of1;
    o4.z = s0b.x * sc0 + of0 + s1b.x * sc1 + of1;
    o4.w = s0b.y * sc0 + of0 + s1b.y * sc1 + of1;
    *(float4*)&out[e] = o4;
}

// ---------------- launch -----------------------------------------------------
extern "C" void kernel_launch(void* const* d_in, const int* in_sizes, int n_in,
                              void* d_out, int out_size) {
    const float* x        = (const float*)d_in[0];
    const float* w_qkv    = (const float*)d_in[1];
    const float* relative = (const float*)d_in[2];
    const float* qg       = (const float*)d_in[3];
    const float* qb       = (const float*)d_in[4];
    const float* sg       = (const float*)d_in[5];
    const float* sb       = (const float*)d_in[6];
    const float* og       = (const float*)d_in[7];
    const float* ob       = (const float*)d_in[8];
    float* out            = (float*)d_out;

    k_init <<<1, 256>>>(relative, w_qkv);
    k_qkv  <<<BTOT, 256>>>(x);
    k_mom  <<<BTOT, 256>>>(qg, qb);
    k_attn <<<BTOT * 2, 224>>>(relative, qg, qb, sg, sb);
    k_out  <<<6272, 256>>>(out, og, ob);
}

// round 14
// speedup vs baseline: 1.1475x; 1.1475x over previous
#include <cuda_runtime.h>
#include <cuda_fp16.h>
#include <math.h>

// Problem constants
#define BTOT   1792          // N*D*H = 1*32*56
#define CH_STR 7168          // 128*56
#define XPLANE 100352        // 32*56*56 == BTOT*56
#define NQKV   100352.0
#define NSIM   5619712.0     // BTOT*56*56
#define EPSBN  1e-5f

typedef unsigned long long u64t;

// ---- packed fp32x2 helpers (sm_103a dual-fp32; lanewise IEEE fp32) ---------
__device__ __forceinline__ u64t pack2(float lo, float hi) {
    u64t d; asm("mov.b64 %0, {%1, %2};" : "=l"(d) : "f"(lo), "f"(hi)); return d;
}
__device__ __forceinline__ float2 unpack2(u64t d) {
    float2 r; asm("mov.b64 {%0, %1}, %2;" : "=f"(r.x), "=f"(r.y) : "l"(d)); return r;
}
__device__ __forceinline__ u64t ffma2(u64t a, u64t b, u64t c) {
    u64t d; asm("fma.rn.f32x2 %0, %1, %2, %3;" : "=l"(d) : "l"(a), "l"(b), "l"(c));
    return d;
}

// ---------------- scratch (device globals; no runtime alloc) ----------------
__device__ float  g_qkv[BTOT * 128 * 56];  // [b][o][i]  o = g*16+cc
__device__ __half g_so [BTOT * 128 * 56];  // [b][o2][i] fp16 (stats kept fp32)
__device__ double g_qsum[128], g_qsq[128];
__device__ double g_ssum[24],  g_ssq[24];
__device__ double g_osum[128], g_osq[128];
__device__ float g_SR[8][56];
__device__ float g_TQ[10][56];
__device__ float g_TK[10][56];

__constant__ int   c_PA[10] = {0,0,0,0,1,1,1,2,2,3};
__constant__ int   c_PB[10] = {0,1,2,3,1,2,3,2,3,3};
__constant__ float c_PW[10] = {1.f,2.f,2.f,2.f,1.f,2.f,2.f,1.f,2.f,1.f};

// ---------------- K_init: zero accumulators + prefix tables -----------------
__global__ void k_init(const float* __restrict__ relative) {
    __shared__ float rel[8][112];
    int t = threadIdx.x;
    if (t < 128) { g_qsum[t] = 0.0; g_qsq[t] = 0.0; g_osum[t] = 0.0; g_osq[t] = 0.0; }
    if (t < 24)  { g_ssum[t] = 0.0; g_ssq[t] = 0.0; }
    for (int idx = t; idx < 8 * 111; idx += 256)
        rel[idx / 111][idx % 111] = relative[idx];
    __syncthreads();
    for (int task = t; task < 448; task += 256) {
        int c = task / 56, i = task % 56;
        float s = 0.f;
        for (int d = 0; d < 56; ++d) s += rel[c][i + d];
        g_SR[c][i] = s;
    }
    for (int task = t; task < 1120; task += 256) {
        int p = task / 56, i = task % 56;
        int pp = p % 10; int isK = (p >= 10) ? 4 : 0;
        int a = c_PA[pp] + isK, bb = c_PB[pp] + isK;
        float s = 0.f;
        for (int d = 0; d < 56; ++d) s += rel[a][i + d] * rel[bb][i + d];
        s *= c_PW[pp];
        if (isK) g_TK[pp][i] = s; else g_TQ[pp][i] = s;
    }
}

// ---------------- K1: qkv = w @ x — split-channel, high-occupancy -----------
// grid = BTOT*2: block (b, half) computes 64 output channels.
// 128 threads: og = t>>3 (4 channels each), ig = t&7 (7 positions each).
// smem 32.3KB -> 7 CTAs/SM (28 warps, 44% occ) for latency hiding.
__global__ void __launch_bounds__(128) k_qkv(const float* __restrict__ x,
                                             const float* __restrict__ w) {
    __shared__ __align__(16) float xs[64][60];     // [c][i]
    __shared__ __align__(16) float wsT[64][66];    // [c][o_local] (stride 66: u64 ok)
    const int b = blockIdx.x >> 1;
    const int half = blockIdx.x & 1;
    const int obase = half * 64;
    const int t = threadIdx.x;

    for (int idx = t; idx < 64 * 14; idx += 128) {
        int c = idx / 14, q4 = idx % 14;
        *(float4*)&xs[c][q4 * 4] = *(const float4*)&x[c * XPLANE + b * 56 + q4 * 4];
    }
    for (int idx = t; idx < 64 * 64; idx += 128) {
        int ol = idx >> 6, c = idx & 63;
        wsT[c][ol] = w[(obase + ol) * 64 + c];
    }
    __syncthreads();

    const int og = t >> 3;                 // 0..15 (4 local channels each)
    const int ig = t & 7;                  // 0..7  (7 positions each)
    const int o0l = og * 4, i0 = ig * 7;
    u64t acc2[2][7];
#pragma unroll
    for (int p = 0; p < 2; ++p)
#pragma unroll
        for (int ii = 0; ii < 7; ++ii) acc2[p][ii] = 0ull;

    for (int c = 0; c < 64; ++c) {
        u64t w01 = *(const u64t*)&wsT[c][o0l];
        u64t w23 = *(const u64t*)&wsT[c][o0l + 2];
#pragma unroll
        for (int ii = 0; ii < 7; ++ii) {
            float xv = xs[c][i0 + ii];
            u64t xx = pack2(xv, xv);
            acc2[0][ii] = ffma2(w01, xx, acc2[0][ii]);
            acc2[1][ii] = ffma2(w23, xx, acc2[1][ii]);
        }
    }
    float* outb = g_qkv + (size_t)b * CH_STR + obase * 56;
#pragma unroll
    for (int p = 0; p < 2; ++p) {
        float s0 = 0.f, sq0 = 0.f, s1 = 0.f, sq1 = 0.f;
#pragma unroll
        for (int ii = 0; ii < 7; ++ii) {
            float2 u = unpack2(acc2[p][ii]);
            outb[(o0l + 2 * p) * 56 + i0 + ii]     = u.x;
            outb[(o0l + 2 * p + 1) * 56 + i0 + ii] = u.y;
            s0 += u.x; sq0 += u.x * u.x;
            s1 += u.y; sq1 += u.y * u.y;
        }
        for (int off = 4; off; off >>= 1) {
            s0  += __shfl_down_sync(0xffffffffu, s0,  off);
            sq0 += __shfl_down_sync(0xffffffffu, sq0, off);
            s1  += __shfl_down_sync(0xffffffffu, s1,  off);
            sq1 += __shfl_down_sync(0xffffffffu, sq1, off);
        }
        if (ig == 0) {
            atomicAdd(&g_qsum[obase + o0l + 2 * p],     (double)s0);
            atomicAdd(&g_qsq [obase + o0l + 2 * p],     (double)sq0);
            atomicAdd(&g_qsum[obase + o0l + 2 * p + 1], (double)s1);
            atomicAdd(&g_qsq [obase + o0l + 2 * p + 1], (double)sq1);
        }
    }
}

// ---------------- K2: analytic sim moments (folds qkv-BN finalize) ----------
__global__ void __launch_bounds__(256) k_mom(const float* __restrict__ qg,
                                             const float* __restrict__ qb) {
    __shared__ float sQs[128], sQo[128];
    const int b = blockIdx.x;
    {
        int o = threadIdx.x;
        if (o < 128) {
            double inv = 1.0 / NQKV;
            double m = g_qsum[o] * inv;
            double v = g_qsq[o] * inv - m * m;
            float sc = qg[o] * rsqrtf((float)v + EPSBN);
            sQs[o] = sc;
            sQo[o] = qb[o] - (float)m * sc;
        }
    }
    __syncthreads();

    const int g = threadIdx.x >> 5;
    const int lane = threadIdx.x & 31;
    const float* base = g_qkv + (size_t)b * CH_STR + g * 16 * 56;

    float part[32];
#pragma unroll
    for (int v = 0; v < 32; ++v) part[v] = 0.f;

#pragma unroll
    for (int ii = 0; ii < 2; ++ii) {
        int i = lane + ii * 32;
        if (i < 56) {
            float q[4], k[4];
#pragma unroll
            for (int c = 0; c < 4; ++c) {
                int oq = g * 16 + c, ok = g * 16 + 4 + c;
                q[c] = base[c * 56 + i]       * sQs[oq] + sQo[oq];
                k[c] = base[(4 + c) * 56 + i] * sQs[ok] + sQo[ok];
            }
#pragma unroll
            for (int c = 0; c < 4; ++c) {
                part[c]     += q[c];
                part[4 + c] += k[c];
                part[28] += q[c] * g_SR[c][i];
                part[30] += k[c] * g_SR[4 + c][i];
            }
#pragma unroll
            for (int p = 0; p < 10; ++p) {
                float pq = q[c_PA[p]] * q[c_PB[p]];
                float pk = k[c_PA[p]] * k[c_PB[p]];
                part[8 + p]  += pq;
                part[18 + p] += pk;
                part[29] += pq * g_TQ[p][i];
                part[31] += pk * g_TK[p][i];
            }
        }
    }
#pragma unroll
    for (int v = 0; v < 32; ++v)
        for (int off = 16; off; off >>= 1)
            part[v] += __shfl_down_sync(0xffffffffu, part[v], off);

    if (lane == 0) {
        float S1 = 0.f, S2 = 0.f;
#pragma unroll
        for (int c = 0; c < 4; ++c) S1 += part[c] * part[4 + c];
#pragma unroll
        for (int p = 0; p < 10; ++p) S2 += c_PW[p] * part[8 + p] * part[18 + p];
        atomicAdd(&g_ssum[g],      (double)S1);
        atomicAdd(&g_ssq [g],      (double)S2);
        atomicAdd(&g_ssum[8 + g],  (double)(0.1f  * part[28]));
        atomicAdd(&g_ssq [8 + g],  (double)(0.01f * part[29]));
        atomicAdd(&g_ssum[16 + g], (double)(0.1f  * part[30]));
        atomicAdd(&g_ssq [16 + g], (double)(0.01f * part[31]));
    }
}

// ---- warp reduce-scatter: 16 partials spread over 8 consecutive lanes ------
__device__ __forceinline__ void reduce_scatter16(const float* av, int tj,
                                                 float& o0, float& o1) {
    float a8[8];
#pragma unroll
    for (int v = 0; v < 8; ++v) {
        float snd = (tj & 1) ? av[v] : av[8 + v];
        float kp  = (tj & 1) ? av[8 + v] : av[v];
        a8[v] = kp + __shfl_xor_sync(0xffffffffu, snd, 1);
    }
    float a4[4];
#pragma unroll
    for (int v = 0; v < 4; ++v) {
        float snd = (tj & 2) ? a8[v] : a8[4 + v];
        float kp  = (tj & 2) ? a8[4 + v] : a8[v];
        a4[v] = kp + __shfl_xor_sync(0xffffffffu, snd, 2);
    }
    float a2[2];
#pragma unroll
    for (int v = 0; v < 2; ++v) {
        float snd = (tj & 4) ? a4[v] : a4[2 + v];
        float kp  = (tj & 4) ? a4[2 + v] : a4[v];
        a2[v] = kp + __shfl_xor_sync(0xffffffffu, snd, 4);
    }
    o0 = a2[0]; o1 = a2[1];
}

// ---------------- K3: attention — grid 3584 = (b, head-half), 4 heads -------
__global__ void __launch_bounds__(224, 5) k_attn(const float* __restrict__ relative,
                                                 const float* __restrict__ qg,
                                                 const float* __restrict__ qb,
                                                 const float* __restrict__ sg,
                                                 const float* __restrict__ sb) {
    __shared__ __align__(16) float qsT[4][56][4];
    __shared__ __align__(16) float ksT[4][56][4];
    __shared__ __align__(16) float vsT[4][56][12];   // 48B stride, conflict-free
    __shared__ __align__(16) __half relQK[111][8];   // {relq[0..3][d], relk[0..3][110-d]}
    __shared__ __align__(16) __half relV[111][8];    // {relv[0..7][d]}
    __shared__ __align__(16) float SB[16][60];
    __shared__ float sQs[64], sQo[64], sC[16];

    const int b = blockIdx.x >> 1;
    const int half = blockIdx.x & 1;
    const int gbase = half * 4;
    const int t = threadIdx.x;

    if (t < 64) {
        int o = half * 64 + t;
        double inv = 1.0 / NQKV;
        double m = g_qsum[o] * inv;
        double v = g_qsq[o] * inv - m * m;
        float sc = qg[o] * rsqrtf((float)v + EPSBN);
        sQs[t] = sc;
        sQo[t] = qb[o] - (float)m * sc;
    } else if (t < 68) {
        int gl = t - 64;
        int g = gbase + gl;
        double inv = 1.0 / NSIM;
        float fac[3] = {1.f, 0.1f, 0.1f};
        float csum = 0.f;
        for (int r = 0; r < 3; ++r) {
            int idx = r * 8 + g;
            double m = g_ssum[idx] * inv;
            double v = g_ssq[idx] * inv - m * m;
            float aa = sg[idx] * rsqrtf((float)v + EPSBN);
            sC[4 * gl + r] = aa * fac[r];
            csum += sb[idx] - (float)m * aa;
        }
        sC[4 * gl + 3] = csum;
    }
    for (int idx = t; idx < 8 * 111; idx += 224) {
        int c = idx / 111, d = idx % 111;
        if (c < 4) relQK[d][c] = __float2half(relative[c * 111 + d]);
        else       relQK[d][c] = __float2half(relative[c * 111 + (110 - d)]);
    }
    for (int idx = t; idx < 8 * 111; idx += 224) {
        int c = idx / 111, d = idx % 111;
        relV[d][c] = __float2half(relative[(8 + c) * 111 + d]);
    }
    __syncthreads();

    {
        const float* src = g_qkv + (size_t)b * CH_STR + half * 64 * 56;
        const int chr = t / 14, i4 = t % 14;
#pragma unroll
        for (int it = 0; it < 4; ++it) {
            int ch = it * 16 + chr;
            float4 v = *(const float4*)&src[ch * 56 + i4 * 4];
            float sc = sQs[ch], of = sQo[ch];
            float vals[4] = {v.x * sc + of, v.y * sc + of, v.z * sc + of, v.w * sc + of};
            int gl = it, cc = chr;
#pragma unroll
            for (int e = 0; e < 4; ++e) {
                int i = i4 * 4 + e;
                if (cc < 4) qsT[gl][i][cc] = vals[e];
                else if (cc < 8) ksT[gl][i][cc - 4] = vals[e];
                else vsT[gl][i][cc - 8] = vals[e];
            }
        }
    }
    __syncthreads();

    const int lane = t & 31;
    const int tj = lane & 7, ig = lane >> 3;
    const int ti = (t >> 5) * 4 + ig;
    const int i0 = ti * 2, j0 = tj * 7;
    const int dbase = i0 - j0 + 49;
    const int chown = ((tj & 1) << 2) | (tj & 2) | ((tj >> 2) & 1);
    const int row_w = t / 14, c4_w = t % 14;

#pragma unroll 1
    for (int gl = 0; gl < 4; ++gl) {
        const int g = gbase + gl;
        const float cqk = sC[4 * gl], cqr = sC[4 * gl + 1], ckr = sC[4 * gl + 2], soff = sC[4 * gl + 3];

        float4 q0v = *(const float4*)qsT[gl][i0];
        float4 q1v = *(const float4*)qsT[gl][i0 + 1];

        float P[14];
        {
            float4 kcur, kprev;
#pragma unroll
            for (int cc = 0; cc < 8; ++cc) {
                int d = dbase + cc;
                uint4 rw = *(const uint4*)relQK[d];
                const __half2* hp = (const __half2*)&rw;
                float2 ra = __half22float2(hp[0]);
                float2 rb = __half22float2(hp[1]);
                float2 rc = __half22float2(hp[2]);
                float2 rd = __half22float2(hp[3]);
                if (cc <= 6) {
                    kcur = *(const float4*)ksT[gl][j0 + 6 - cc];
                    float qk = q0v.x * kcur.x + q0v.y * kcur.y + q0v.z * kcur.z + q0v.w * kcur.w;
                    float qr = q0v.x * ra.x + q0v.y * ra.y + q0v.z * rb.x + q0v.w * rb.y;
                    float kr = kcur.x * rc.x + kcur.y * rc.y + kcur.z * rd.x + kcur.w * rd.y;
                    P[6 - cc] = fmaf(cqk, qk, fmaf(cqr, qr, fmaf(ckr, kr, soff)));
                }
                if (cc >= 1) {
                    float qk = q1v.x * kprev.x + q1v.y * kprev.y + q1v.z * kprev.z + q1v.w * kprev.w;
                    float qr = q1v.x * ra.x + q1v.y * ra.y + q1v.z * rb.x + q1v.w * rb.y;
                    float kr = kprev.x * rc.x + kprev.y * rc.y + kprev.z * rd.x + kprev.w * rd.y;
                    P[7 + 7 - cc] = fmaf(cqk, qk, fmaf(cqr, qr, fmaf(ckr, kr, soff)));
                }
                kprev = kcur;
            }
        }

        float rinv0, rinv1;
        {
            float rs0 = 0.f, rs1 = 0.f;
#pragma unroll
            for (int jj = 0; jj < 7; ++jj) {
                float p0 = __expf(P[jj]);
                float p1 = __expf(P[7 + jj]);
                P[jj] = p0; P[7 + jj] = p1;
                rs0 += p0; rs1 += p1;
            }
#pragma unroll
            for (int m = 1; m < 8; m <<= 1) {
                rs0 += __shfl_xor_sync(0xffffffffu, rs0, m);
                rs1 += __shfl_xor_sync(0xffffffffu, rs1, m);
            }
            rinv0 = 1.0f / rs0;
            rinv1 = 1.0f / rs1;
        }

        {
            u64t av2[8];
#pragma unroll
            for (int v = 0; v < 8; ++v) av2[v] = 0ull;
#pragma unroll
            for (int jj = 0; jj < 7; ++jj) {
                const float* vr = &vsT[gl][j0 + jj][0];
                u64t v01 = *(const u64t*)&vr[0];
                u64t v23 = *(const u64t*)&vr[2];
                u64t v45 = *(const u64t*)&vr[4];
                u64t v67 = *(const u64t*)&vr[6];
                u64t pp0 = pack2(P[jj], P[jj]);
                u64t pp1 = pack2(P[7 + jj], P[7 + jj]);
                av2[0] = ffma2(pp0, v01, av2[0]);
                av2[1] = ffma2(pp1, v01, av2[1]);
                av2[2] = ffma2(pp0, v23, av2[2]);
                av2[3] = ffma2(pp1, v23, av2[3]);
                av2[4] = ffma2(pp0, v45, av2[4]);
                av2[5] = ffma2(pp1, v45, av2[5]);
                av2[6] = ffma2(pp0, v67, av2[6]);
                av2[7] = ffma2(pp1, v67, av2[7]);
            }
            float av[16];
#pragma unroll
            for (int cp = 0; cp < 4; ++cp) {
#pragma unroll
                for (int r = 0; r < 2; ++r) {
                    float2 u = unpack2(av2[cp * 2 + r]);
                    av[2 * (2 * cp) + r]     = u.x;
                    av[2 * (2 * cp + 1) + r] = u.y;
                }
            }
            float s0, s1;
            reduce_scatter16(av, tj, s0, s1);
            SB[2 * chown][i0]     = s0 * rinv0;
            SB[2 * chown][i0 + 1] = s1 * rinv1;
        }

        {
            float av[16];
#pragma unroll
            for (int v = 0; v < 16; ++v) av[v] = 0.f;
#pragma unroll
            for (int cc = 0; cc < 8; ++cc) {
                int d = dbase + cc;
                uint4 rw = *(const uint4*)relV[d];
                const __half2* hp = (const __half2*)&rw;
                float2 va = __half22float2(hp[0]);
                float2 vb = __half22float2(hp[1]);
                float2 vc = __half22float2(hp[2]);
                float2 vd = __half22float2(hp[3]);
                if (cc <= 6) {
                    float p = P[6 - cc];
                    av[0] += p * va.x; av[2]  += p * va.y; av[4]  += p * vb.x; av[6]  += p * vb.y;
                    av[8] += p * vc.x; av[10] += p * vc.y; av[12] += p * vd.x; av[14] += p * vd.y;
                }
                if (cc >= 1) {
                    float p = P[7 + 7 - cc];
                    av[1] += p * va.x; av[3]  += p * va.y; av[5]  += p * vb.x; av[7]  += p * vb.y;
                    av[9] += p * vc.x; av[11] += p * vc.y; av[13] += p * vd.x; av[15] += p * vd.y;
                }
            }
            float s0, s1;
            reduce_scatter16(av, tj, s0, s1);
            SB[2 * chown + 1][i0]     = s0 * rinv0 * 0.1f;
            SB[2 * chown + 1][i0 + 1] = s1 * rinv1 * 0.1f;
        }
        __syncthreads();

        {
            float4 v4 = *(const float4*)&SB[row_w][c4_w * 4];
            __half2 h0 = __floats2half2_rn(v4.x, v4.y);
            __half2 h1 = __floats2half2_rn(v4.z, v4.w);
            __half* ob = g_so + (size_t)b * CH_STR + g * 16 * 56 + row_w * 56 + c4_w * 4;
            uint2 st;
            st.x = *(unsigned*)&h0;
            st.y = *(unsigned*)&h1;
            *(uint2*)ob = st;
        }

        if (t < 128) {
            int row = t >> 3, sub = t & 7;
            float s1 = 0.f, s2 = 0.f;
#pragma unroll
            for (int e = 0; e < 7; ++e) {
                float v = SB[row][sub * 7 + e];
                s1 += v; s2 += v * v;
            }
#pragma unroll
            for (int m = 1; m < 8; m <<= 1) {
                s1 += __shfl_xor_sync(0xffffffffu, s1, m);
                s2 += __shfl_xor_sync(0xffffffffu, s2, m);
            }
            if (sub == 0) {
                atomicAdd(&g_osum[g * 16 + row], (double)s1);
                atomicAdd(&g_osq [g * 16 + row], (double)s2);
            }
        }
        __syncthreads();
    }
}

// ---------------- K4: out BN (folded finalize) + pair-sum + layout ----------
__global__ void __launch_bounds__(256) k_out(float* __restrict__ out,
                                             const float* __restrict__ og,
                                             const float* __restrict__ ob) {
    __shared__ float sOs[128], sOo[128];
    {
        int o = threadIdx.x;
        if (o < 128) {
            double inv = 1.0 / NQKV;
            double m = g_osum[o] * inv;
            double v = g_osq[o] * inv - m * m;
            float sc = og[o] * rsqrtf((float)v + EPSBN);
            sOs[o] = sc;
            sOo[o] = ob[o] - (float)m * sc;
        }
    }
    __syncthreads();
    int idx = blockIdx.x * 256 + threadIdx.x;
    if (idx >= 1605632) return;
    int e  = idx * 4;
    int cp = e / XPLANE;
    int r  = e % XPLANE;
    int bq = r / 56, i = r % 56;
    const __half* base = g_so + (size_t)bq * CH_STR + (2 * cp) * 56 + i;
    uint2 a = *(const uint2*)base;
    uint2 bb = *(const uint2*)(base + 56);
    __half2 ha0, ha1, hb0, hb1;
    *(unsigned*)&ha0 = a.x;  *(unsigned*)&ha1 = a.y;
    *(unsigned*)&hb0 = bb.x; *(unsigned*)&hb1 = bb.y;
    float2 s0a = __half22float2(ha0), s0b = __half22float2(ha1);
    float2 s1a = __half22float2(hb0), s1b = __half22float2(hb1);
    float sc0 = sOs[2 * cp], of0 = sOo[2 * cp];
    float sc1 = sOs[2 * cp + 1], of1 = sOo[2 * cp + 1];
    float4 o4;
    o4.x = s0a.x * sc0 + of0 + s1a.x * sc1 + of1;
    o4.y = s0a.y * sc0 + of0 + s1a.y * sc1 + of1;
    o4.z = s0b.x * sc0 + of0 + s1b.x * sc1 + of1;
    o4.w = s0b.y * sc0 + of0 + s1b.y * sc1 + of1;
    *(float4*)&out[e] = o4;
}

// ---------------- launch -----------------------------------------------------
extern "C" void kernel_launch(void* const* d_in, const int* in_sizes, int n_in,
                              void* d_out, int out_size) {
    const float* x        = (const float*)d_in[0];
    const float* w_qkv    = (const float*)d_in[1];
    const float* relative = (const float*)d_in[2];
    const float* qg       = (const float*)d_in[3];
    const float* qb       = (const float*)d_in[4];
    const float* sg       = (const float*)d_in[5];
    const float* sb       = (const float*)d_in[6];
    const float* og       = (const float*)d_in[7];
    const float* ob       = (const float*)d_in[8];
    float* out            = (float*)d_out;

    k_init <<<1, 256>>>(relative);
    k_qkv  <<<BTOT * 2, 128>>>(x, w_qkv);
    k_mom  <<<BTOT, 256>>>(qg, qb);
    k_attn <<<BTOT * 2, 224>>>(relative, qg, qb, sg, sb);
    k_out  <<<6272, 256>>>(out, og, ob);
}

// round 15
// speedup vs baseline: 1.1768x; 1.0256x over previous
#include <cuda_runtime.h>
#include <cuda_fp16.h>
#include <math.h>

// Problem constants
#define BTOT   1792          // N*D*H = 1*32*56
#define CH_STR 7168          // 128*56
#define XPLANE 100352        // 32*56*56 == BTOT*56
#define NQKV   100352.0
#define NSIM   5619712.0     // BTOT*56*56
#define EPSBN  1e-5f

typedef unsigned long long u64t;

// ---- packed fp32x2 helpers (sm_103a dual-fp32; lanewise IEEE fp32) ---------
__device__ __forceinline__ u64t pack2(float lo, float hi) {
    u64t d; asm("mov.b64 %0, {%1, %2};" : "=l"(d) : "f"(lo), "f"(hi)); return d;
}
__device__ __forceinline__ float2 unpack2(u64t d) {
    float2 r; asm("mov.b64 {%0, %1}, %2;" : "=f"(r.x), "=f"(r.y) : "l"(d)); return r;
}
__device__ __forceinline__ u64t ffma2(u64t a, u64t b, u64t c) {
    u64t d; asm("fma.rn.f32x2 %0, %1, %2, %3;" : "=l"(d) : "l"(a), "l"(b), "l"(c));
    return d;
}

// ---------------- scratch (device globals; no runtime alloc) ----------------
__device__ float  g_qkv[BTOT * 128 * 56];  // [b][o][i]  o = g*16+cc
__device__ __half g_so [BTOT * 128 * 56];  // [b][o2][i] fp16 (stats kept fp32)
__device__ double g_qsum[128], g_qsq[128]; // zeroed by k_out (prev invocation)
__device__ double g_ssum[24],  g_ssq[24];  // zeroed by k_out (prev invocation)
__device__ double g_osum[128], g_osq[128]; // zeroed by k_qkv block 0
__device__ float g_SR[8][56];
__device__ float g_TQ[10][56];
__device__ float g_TK[10][56];

__constant__ int   c_PA[10] = {0,0,0,0,1,1,1,2,2,3};
__constant__ int   c_PB[10] = {0,1,2,3,1,2,3,2,3,3};
__constant__ float c_PW[10] = {1.f,2.f,2.f,2.f,1.f,2.f,2.f,1.f,2.f,1.f};

// ---------------- K1: qkv = w @ x — split-channel, high-occupancy -----------
// grid = BTOT*2: block (b, half) computes 64 output channels.
// Blocks 0..13 additionally compute the rel prefix tables (overlapped with
// GEMM work; tables consumed only by the NEXT kernel, k_mom).
// Block 0 zeroes g_osum/g_osq (consumed only by later kernels).
__global__ void __launch_bounds__(128) k_qkv(const float* __restrict__ x,
                                             const float* __restrict__ w,
                                             const float* __restrict__ relative) {
    __shared__ __align__(16) float xs[64][60];     // [c][i]
    __shared__ __align__(16) float wsT[64][66];    // [c][o_local]
    const int b = blockIdx.x >> 1;
    const int half = blockIdx.x & 1;
    const int obase = half * 64;
    const int t = threadIdx.x;

    // ---- side duties (no intra-kernel consumer; visible at kernel end) ----
    if (blockIdx.x == 0 && t < 128) { g_osum[t] = 0.0; g_osq[t] = 0.0; }
    if (blockIdx.x < 14) {
        int task = blockIdx.x * 128 + t;
        if (task < 448) {
            int c = task / 56, i = task % 56;
            float s = 0.f;
            for (int d = 0; d < 56; ++d) s += relative[c * 111 + i + d];
            g_SR[c][i] = s;
        } else if (task < 1568) {
            int p = (task - 448) / 56, i = (task - 448) % 56;
            int pp = p % 10; int isK = (p >= 10) ? 4 : 0;
            int a = c_PA[pp] + isK, bb = c_PB[pp] + isK;
            float s = 0.f;
            for (int d = 0; d < 56; ++d)
                s += relative[a * 111 + i + d] * relative[bb * 111 + i + d];
            s *= c_PW[pp];
            if (isK) g_TK[pp][i] = s; else g_TQ[pp][i] = s;
        }
    }

    for (int idx = t; idx < 64 * 14; idx += 128) {
        int c = idx / 14, q4 = idx % 14;
        *(float4*)&xs[c][q4 * 4] = *(const float4*)&x[c * XPLANE + b * 56 + q4 * 4];
    }
    for (int idx = t; idx < 64 * 64; idx += 128) {
        int ol = idx >> 6, c = idx & 63;
        wsT[c][ol] = w[(obase + ol) * 64 + c];
    }
    __syncthreads();

    const int og = t >> 3;                 // 0..15 (4 local channels each)
    const int ig = t & 7;                  // 0..7  (7 positions each)
    const int o0l = og * 4, i0 = ig * 7;
    u64t acc2[2][7];
#pragma unroll
    for (int p = 0; p < 2; ++p)
#pragma unroll
        for (int ii = 0; ii < 7; ++ii) acc2[p][ii] = 0ull;

    for (int c = 0; c < 64; ++c) {
        u64t w01 = *(const u64t*)&wsT[c][o0l];
        u64t w23 = *(const u64t*)&wsT[c][o0l + 2];
#pragma unroll
        for (int ii = 0; ii < 7; ++ii) {
            float xv = xs[c][i0 + ii];
            u64t xx = pack2(xv, xv);
            acc2[0][ii] = ffma2(w01, xx, acc2[0][ii]);
            acc2[1][ii] = ffma2(w23, xx, acc2[1][ii]);
        }
    }
    float* outb = g_qkv + (size_t)b * CH_STR + obase * 56;
#pragma unroll
    for (int p = 0; p < 2; ++p) {
        float s0 = 0.f, sq0 = 0.f, s1 = 0.f, sq1 = 0.f;
#pragma unroll
        for (int ii = 0; ii < 7; ++ii) {
            float2 u = unpack2(acc2[p][ii]);
            outb[(o0l + 2 * p) * 56 + i0 + ii]     = u.x;
            outb[(o0l + 2 * p + 1) * 56 + i0 + ii] = u.y;
            s0 += u.x; sq0 += u.x * u.x;
            s1 += u.y; sq1 += u.y * u.y;
        }
        for (int off = 4; off; off >>= 1) {
            s0  += __shfl_down_sync(0xffffffffu, s0,  off);
            sq0 += __shfl_down_sync(0xffffffffu, sq0, off);
            s1  += __shfl_down_sync(0xffffffffu, s1,  off);
            sq1 += __shfl_down_sync(0xffffffffu, sq1, off);
        }
        if (ig == 0) {
            atomicAdd(&g_qsum[obase + o0l + 2 * p],     (double)s0);
            atomicAdd(&g_qsq [obase + o0l + 2 * p],     (double)sq0);
            atomicAdd(&g_qsum[obase + o0l + 2 * p + 1], (double)s1);
            atomicAdd(&g_qsq [obase + o0l + 2 * p + 1], (double)sq1);
        }
    }
}

// ---------------- K2: analytic sim moments (folds qkv-BN finalize) ----------
__global__ void __launch_bounds__(256) k_mom(const float* __restrict__ qg,
                                             const float* __restrict__ qb) {
    __shared__ float sQs[128], sQo[128];
    const int b = blockIdx.x;
    {
        int o = threadIdx.x;
        if (o < 128) {
            double inv = 1.0 / NQKV;
            double m = g_qsum[o] * inv;
            double v = g_qsq[o] * inv - m * m;
            float sc = qg[o] * rsqrtf((float)v + EPSBN);
            sQs[o] = sc;
            sQo[o] = qb[o] - (float)m * sc;
        }
    }
    __syncthreads();

    const int g = threadIdx.x >> 5;
    const int lane = threadIdx.x & 31;
    const float* base = g_qkv + (size_t)b * CH_STR + g * 16 * 56;

    float part[32];
#pragma unroll
    for (int v = 0; v < 32; ++v) part[v] = 0.f;

#pragma unroll
    for (int ii = 0; ii < 2; ++ii) {
        int i = lane + ii * 32;
        if (i < 56) {
            float q[4], k[4];
#pragma unroll
            for (int c = 0; c < 4; ++c) {
                int oq = g * 16 + c, ok = g * 16 + 4 + c;
                q[c] = base[c * 56 + i]       * sQs[oq] + sQo[oq];
                k[c] = base[(4 + c) * 56 + i] * sQs[ok] + sQo[ok];
            }
#pragma unroll
            for (int c = 0; c < 4; ++c) {
                part[c]     += q[c];
                part[4 + c] += k[c];
                part[28] += q[c] * g_SR[c][i];
                part[30] += k[c] * g_SR[4 + c][i];
            }
#pragma unroll
            for (int p = 0; p < 10; ++p) {
                float pq = q[c_PA[p]] * q[c_PB[p]];
                float pk = k[c_PA[p]] * k[c_PB[p]];
                part[8 + p]  += pq;
                part[18 + p] += pk;
                part[29] += pq * g_TQ[p][i];
                part[31] += pk * g_TK[p][i];
            }
        }
    }
#pragma unroll
    for (int v = 0; v < 32; ++v)
        for (int off = 16; off; off >>= 1)
            part[v] += __shfl_down_sync(0xffffffffu, part[v], off);

    if (lane == 0) {
        float S1 = 0.f, S2 = 0.f;
#pragma unroll
        for (int c = 0; c < 4; ++c) S1 += part[c] * part[4 + c];
#pragma unroll
        for (int p = 0; p < 10; ++p) S2 += c_PW[p] * part[8 + p] * part[18 + p];
        atomicAdd(&g_ssum[g],      (double)S1);
        atomicAdd(&g_ssq [g],      (double)S2);
        atomicAdd(&g_ssum[8 + g],  (double)(0.1f  * part[28]));
        atomicAdd(&g_ssq [8 + g],  (double)(0.01f * part[29]));
        atomicAdd(&g_ssum[16 + g], (double)(0.1f  * part[30]));
        atomicAdd(&g_ssq [16 + g], (double)(0.01f * part[31]));
    }
}

// ---- warp reduce-scatter: 16 partials spread over 8 consecutive lanes ------
__device__ __forceinline__ void reduce_scatter16(const float* av, int tj,
                                                 float& o0, float& o1) {
    float a8[8];
#pragma unroll
    for (int v = 0; v < 8; ++v) {
        float snd = (tj & 1) ? av[v] : av[8 + v];
        float kp  = (tj & 1) ? av[8 + v] : av[v];
        a8[v] = kp + __shfl_xor_sync(0xffffffffu, snd, 1);
    }
    float a4[4];
#pragma unroll
    for (int v = 0; v < 4; ++v) {
        float snd = (tj & 2) ? a8[v] : a8[4 + v];
        float kp  = (tj & 2) ? a8[4 + v] : a8[v];
        a4[v] = kp + __shfl_xor_sync(0xffffffffu, snd, 2);
    }
    float a2[2];
#pragma unroll
    for (int v = 0; v < 2; ++v) {
        float snd = (tj & 4) ? a4[v] : a4[2 + v];
        float kp  = (tj & 4) ? a4[2 + v] : a4[v];
        a2[v] = kp + __shfl_xor_sync(0xffffffffu, snd, 4);
    }
    o0 = a2[0]; o1 = a2[1];
}

// ---------------- K3: attention — grid 3584 = (b, head-half), 4 heads -------
__global__ void __launch_bounds__(224, 5) k_attn(const float* __restrict__ relative,
                                                 const float* __restrict__ qg,
                                                 const float* __restrict__ qb,
                                                 const float* __restrict__ sg,
                                                 const float* __restrict__ sb) {
    __shared__ __align__(16) float qsT[4][56][4];
    __shared__ __align__(16) float ksT[4][56][4];
    __shared__ __align__(16) float vsT[4][56][12];   // 48B stride, conflict-free
    __shared__ __align__(16) __half relQK[111][8];   // {relq[0..3][d], relk[0..3][110-d]}
    __shared__ __align__(16) __half relV[111][8];    // {relv[0..7][d]}
    __shared__ __align__(16) float SB[16][60];
    __shared__ float sQs[64], sQo[64], sC[16];

    const int b = blockIdx.x >> 1;
    const int half = blockIdx.x & 1;
    const int gbase = half * 4;
    const int t = threadIdx.x;

    if (t < 64) {
        int o = half * 64 + t;
        double inv = 1.0 / NQKV;
        double m = g_qsum[o] * inv;
        double v = g_qsq[o] * inv - m * m;
        float sc = qg[o] * rsqrtf((float)v + EPSBN);
        sQs[t] = sc;
        sQo[t] = qb[o] - (float)m * sc;
    } else if (t < 68) {
        int gl = t - 64;
        int g = gbase + gl;
        double inv = 1.0 / NSIM;
        float fac[3] = {1.f, 0.1f, 0.1f};
        float csum = 0.f;
        for (int r = 0; r < 3; ++r) {
            int idx = r * 8 + g;
            double m = g_ssum[idx] * inv;
            double v = g_ssq[idx] * inv - m * m;
            float aa = sg[idx] * rsqrtf((float)v + EPSBN);
            sC[4 * gl + r] = aa * fac[r];
            csum += sb[idx] - (float)m * aa;
        }
        sC[4 * gl + 3] = csum;
    }
    for (int idx = t; idx < 8 * 111; idx += 224) {
        int c = idx / 111, d = idx % 111;
        if (c < 4) relQK[d][c] = __float2half(relative[c * 111 + d]);
        else       relQK[d][c] = __float2half(relative[c * 111 + (110 - d)]);
    }
    for (int idx = t; idx < 8 * 111; idx += 224) {
        int c = idx / 111, d = idx % 111;
        relV[d][c] = __float2half(relative[(8 + c) * 111 + d]);
    }
    __syncthreads();

    {
        const float* src = g_qkv + (size_t)b * CH_STR + half * 64 * 56;
        const int chr = t / 14, i4 = t % 14;
#pragma unroll
        for (int it = 0; it < 4; ++it) {
            int ch = it * 16 + chr;
            float4 v = *(const float4*)&src[ch * 56 + i4 * 4];
            float sc = sQs[ch], of = sQo[ch];
            float vals[4] = {v.x * sc + of, v.y * sc + of, v.z * sc + of, v.w * sc + of};
            int gl = it, cc = chr;
#pragma unroll
            for (int e = 0; e < 4; ++e) {
                int i = i4 * 4 + e;
                if (cc < 4) qsT[gl][i][cc] = vals[e];
                else if (cc < 8) ksT[gl][i][cc - 4] = vals[e];
                else vsT[gl][i][cc - 8] = vals[e];
            }
        }
    }
    __syncthreads();

    const int lane = t & 31;
    const int tj = lane & 7, ig = lane >> 3;
    const int ti = (t >> 5) * 4 + ig;
    const int i0 = ti * 2, j0 = tj * 7;
    const int dbase = i0 - j0 + 49;
    const int chown = ((tj & 1) << 2) | (tj & 2) | ((tj >> 2) & 1);
    const int row_w = t / 14, c4_w = t % 14;

#pragma unroll 1
    for (int gl = 0; gl < 4; ++gl) {
        const int g = gbase + gl;
        const float cqk = sC[4 * gl], cqr = sC[4 * gl + 1], ckr = sC[4 * gl + 2], soff = sC[4 * gl + 3];

        float4 q0v = *(const float4*)qsT[gl][i0];
        float4 q1v = *(const float4*)qsT[gl][i0 + 1];

        float P[14];
        {
            float4 kcur, kprev;
#pragma unroll
            for (int cc = 0; cc < 8; ++cc) {
                int d = dbase + cc;
                uint4 rw = *(const uint4*)relQK[d];
                const __half2* hp = (const __half2*)&rw;
                float2 ra = __half22float2(hp[0]);
                float2 rb = __half22float2(hp[1]);
                float2 rc = __half22float2(hp[2]);
                float2 rd = __half22float2(hp[3]);
                if (cc <= 6) {
                    kcur = *(const float4*)ksT[gl][j0 + 6 - cc];
                    float qk = q0v.x * kcur.x + q0v.y * kcur.y + q0v.z * kcur.z + q0v.w * kcur.w;
                    float qr = q0v.x * ra.x + q0v.y * ra.y + q0v.z * rb.x + q0v.w * rb.y;
                    float kr = kcur.x * rc.x + kcur.y * rc.y + kcur.z * rd.x + kcur.w * rd.y;
                    P[6 - cc] = fmaf(cqk, qk, fmaf(cqr, qr, fmaf(ckr, kr, soff)));
                }
                if (cc >= 1) {
                    float qk = q1v.x * kprev.x + q1v.y * kprev.y + q1v.z * kprev.z + q1v.w * kprev.w;
                    float qr = q1v.x * ra.x + q1v.y * ra.y + q1v.z * rb.x + q1v.w * rb.y;
                    float kr = kprev.x * rc.x + kprev.y * rc.y + kprev.z * rd.x + kprev.w * rd.y;
                    P[7 + 7 - cc] = fmaf(cqk, qk, fmaf(cqr, qr, fmaf(ckr, kr, soff)));
                }
                kprev = kcur;
            }
        }

        float rinv0, rinv1;
        {
            float rs0 = 0.f, rs1 = 0.f;
#pragma unroll
            for (int jj = 0; jj < 7; ++jj) {
                float p0 = __expf(P[jj]);
                float p1 = __expf(P[7 + jj]);
                P[jj] = p0; P[7 + jj] = p1;
                rs0 += p0; rs1 += p1;
            }
#pragma unroll
            for (int m = 1; m < 8; m <<= 1) {
                rs0 += __shfl_xor_sync(0xffffffffu, rs0, m);
                rs1 += __shfl_xor_sync(0xffffffffu, rs1, m);
            }
            rinv0 = 1.0f / rs0;
            rinv1 = 1.0f / rs1;
        }

        {
            u64t av2[8];
#pragma unroll
            for (int v = 0; v < 8; ++v) av2[v] = 0ull;
#pragma unroll
            for (int jj = 0; jj < 7; ++jj) {
                const float* vr = &vsT[gl][j0 + jj][0];
                u64t v01 = *(const u64t*)&vr[0];
                u64t v23 = *(const u64t*)&vr[2];
                u64t v45 = *(const u64t*)&vr[4];
                u64t v67 = *(const u64t*)&vr[6];
                u64t pp0 = pack2(P[jj], P[jj]);
                u64t pp1 = pack2(P[7 + jj], P[7 + jj]);
                av2[0] = ffma2(pp0, v01, av2[0]);
                av2[1] = ffma2(pp1, v01, av2[1]);
                av2[2] = ffma2(pp0, v23, av2[2]);
                av2[3] = ffma2(pp1, v23, av2[3]);
                av2[4] = ffma2(pp0, v45, av2[4]);
                av2[5] = ffma2(pp1, v45, av2[5]);
                av2[6] = ffma2(pp0, v67, av2[6]);
                av2[7] = ffma2(pp1, v67, av2[7]);
            }
            float av[16];
#pragma unroll
            for (int cp = 0; cp < 4; ++cp) {
#pragma unroll
                for (int r = 0; r < 2; ++r) {
                    float2 u = unpack2(av2[cp * 2 + r]);
                    av[2 * (2 * cp) + r]     = u.x;
                    av[2 * (2 * cp + 1) + r] = u.y;
                }
            }
            float s0, s1;
            reduce_scatter16(av, tj, s0, s1);
            SB[2 * chown][i0]     = s0 * rinv0;
            SB[2 * chown][i0 + 1] = s1 * rinv1;
        }

        {
            float av[16];
#pragma unroll
            for (int v = 0; v < 16; ++v) av[v] = 0.f;
#pragma unroll
            for (int cc = 0; cc < 8; ++cc) {
                int d = dbase + cc;
                uint4 rw = *(const uint4*)relV[d];
                const __half2* hp = (const __half2*)&rw;
                float2 va = __half22float2(hp[0]);
                float2 vb = __half22float2(hp[1]);
                float2 vc = __half22float2(hp[2]);
                float2 vd = __half22float2(hp[3]);
                if (cc <= 6) {
                    float p = P[6 - cc];
                    av[0] += p * va.x; av[2]  += p * va.y; av[4]  += p * vb.x; av[6]  += p * vb.y;
                    av[8] += p * vc.x; av[10] += p * vc.y; av[12] += p * vd.x; av[14] += p * vd.y;
                }
                if (cc >= 1) {
                    float p = P[7 + 7 - cc];
                    av[1] += p * va.x; av[3]  += p * va.y; av[5]  += p * vb.x; av[7]  += p * vb.y;
                    av[9] += p * vc.x; av[11] += p * vc.y; av[13] += p * vd.x; av[15] += p * vd.y;
                }
            }
            float s0, s1;
            reduce_scatter16(av, tj, s0, s1);
            SB[2 * chown + 1][i0]     = s0 * rinv0 * 0.1f;
            SB[2 * chown + 1][i0 + 1] = s1 * rinv1 * 0.1f;
        }
        __syncthreads();

        {
            float4 v4 = *(const float4*)&SB[row_w][c4_w * 4];
            __half2 h0 = __floats2half2_rn(v4.x, v4.y);
            __half2 h1 = __floats2half2_rn(v4.z, v4.w);
            __half* ob = g_so + (size_t)b * CH_STR + g * 16 * 56 + row_w * 56 + c4_w * 4;
            uint2 st;
            st.x = *(unsigned*)&h0;
            st.y = *(unsigned*)&h1;
            *(uint2*)ob = st;
        }

        if (t < 128) {
            int row = t >> 3, sub = t & 7;
            float s1 = 0.f, s2 = 0.f;
#pragma unroll
            for (int e = 0; e < 7; ++e) {
                float v = SB[row][sub * 7 + e];
                s1 += v; s2 += v * v;
            }
#pragma unroll
            for (int m = 1; m < 8; m <<= 1) {
                s1 += __shfl_xor_sync(0xffffffffu, s1, m);
                s2 += __shfl_xor_sync(0xffffffffu, s2, m);
            }
            if (sub == 0) {
                atomicAdd(&g_osum[g * 16 + row], (double)s1);
                atomicAdd(&g_osq [g * 16 + row], (double)s2);
            }
        }
        __syncthreads();
    }
}

// ---------------- K4: out BN + pair-sum + layout; zeroes q/s accums ---------
__global__ void __launch_bounds__(256) k_out(float* __restrict__ out,
                                             const float* __restrict__ og,
                                             const float* __restrict__ ob) {
    __shared__ float sOs[128], sOo[128];
    {
        int o = threadIdx.x;
        if (o < 128) {
            double inv = 1.0 / NQKV;
            double m = g_osum[o] * inv;
            double v = g_osq[o] * inv - m * m;
            float sc = og[o] * rsqrtf((float)v + EPSBN);
            sOs[o] = sc;
            sOo[o] = ob[o] - (float)m * sc;
        }
    }
    // zero the accumulators consumed earlier this invocation (for next call);
    // no kernel after this one reads them, and no k_out thread reads them.
    if (blockIdx.x == 0) {
        int o = threadIdx.x;
        if (o < 128) { g_qsum[o] = 0.0; g_qsq[o] = 0.0; }
        if (o >= 128 && o < 152) { g_ssum[o - 128] = 0.0; g_ssq[o - 128] = 0.0; }
    }
    __syncthreads();
    int idx = blockIdx.x * 256 + threadIdx.x;
    if (idx >= 1605632) return;
    int e  = idx * 4;
    int cp = e / XPLANE;
    int r  = e % XPLANE;
    int bq = r / 56, i = r % 56;
    const __half* base = g_so + (size_t)bq * CH_STR + (2 * cp) * 56 + i;
    uint2 a = *(const uint2*)base;
    uint2 bb = *(const uint2*)(base + 56);
    __half2 ha0, ha1, hb0, hb1;
    *(unsigned*)&ha0 = a.x;  *(unsigned*)&ha1 = a.y;
    *(unsigned*)&hb0 = bb.x; *(unsigned*)&hb1 = bb.y;
    float2 s0a = __half22float2(ha0), s0b = __half22float2(ha1);
    float2 s1a = __half22float2(hb0), s1b = __half22float2(hb1);
    float sc0 = sOs[2 * cp], of0 = sOo[2 * cp];
    float sc1 = sOs[2 * cp + 1], of1 = sOo[2 * cp + 1];
    float4 o4;
    o4.x = s0a.x * sc0 + of0 + s1a.x * sc1 + of1;
    o4.y = s0a.y * sc0 + of0 + s1a.y * sc1 + of1;
    o4.z = s0b.x * sc0 + of0 + s1b.x * sc1 + of1;
    o4.w = s0b.y * sc0 + of0 + s1b.y * sc1 + of1;
    *(float4*)&out[e] = o4;
}

// ---------------- launch -----------------------------------------------------
extern "C" void kernel_launch(void* const* d_in, const int* in_sizes, int n_in,
                              void* d_out, int out_size) {
    const float* x        = (const float*)d_in[0];
    const float* w_qkv    = (const float*)d_in[1];
    const float* relative = (const float*)d_in[2];
    const float* qg       = (const float*)d_in[3];
    const float* qb       = (const float*)d_in[4];
    const float* sg       = (const float*)d_in[5];
    const float* sb       = (const float*)d_in[6];
    const float* og       = (const float*)d_in[7];
    const float* ob       = (const float*)d_in[8];
    float* out            = (float*)d_out;

    k_qkv  <<<BTOT * 2, 128>>>(x, w_qkv, relative);
    k_mom  <<<BTOT, 256>>>(qg, qb);
    k_attn <<<BTOT * 2, 224>>>(relative, qg, qb, sg, sb);
    k_out  <<<6272, 256>>>(out, og, ob);
}

// round 16
// speedup vs baseline: 1.2171x; 1.0342x over previous
#include <cuda_runtime.h>
#include <cuda_fp16.h>
#include <math.h>

// Problem constants
#define BTOT   1792          // N*D*H = 1*32*56
#define CH_STR 7168          // 128*56
#define XPLANE 100352        // 32*56*56 == BTOT*56
#define NQKV   100352.0
#define NSIM   5619712.0     // BTOT*56*56
#define EPSBN  1e-5f

typedef unsigned long long u64t;

// ---- packed fp32x2 helpers (sm_103a dual-fp32; lanewise IEEE fp32) ---------
__device__ __forceinline__ u64t pack2(float lo, float hi) {
    u64t d; asm("mov.b64 %0, {%1, %2};" : "=l"(d) : "f"(lo), "f"(hi)); return d;
}
__device__ __forceinline__ float2 unpack2(u64t d) {
    float2 r; asm("mov.b64 {%0, %1}, %2;" : "=f"(r.x), "=f"(r.y) : "l"(d)); return r;
}
__device__ __forceinline__ u64t ffma2(u64t a, u64t b, u64t c) {
    u64t d; asm("fma.rn.f32x2 %0, %1, %2, %3;" : "=l"(d) : "l"(a), "l"(b), "l"(c));
    return d;
}

// ---------------- scratch (device globals; no runtime alloc) ----------------
__device__ float  g_qkv[BTOT * 128 * 56];  // [b][o][i]  o = g*16+cc
__device__ __half g_so [BTOT * 128 * 56];  // [b][o2][i] fp16 (stats kept fp32)
__device__ double g_qsum[128], g_qsq[128]; // zeroed by k_out (prev invocation)
__device__ double g_ssum[24],  g_ssq[24];  // zeroed by k_out (prev invocation)
__device__ double g_osum[128], g_osq[128]; // zeroed by k_qkv block 0
__device__ float g_SR[8][56];
__device__ float g_TQ[10][56];
__device__ float g_TK[10][56];
// fp16 rel tables, precomputed by k_qkv side blocks:
//   g_relh[0][d] = { relq[0..3][d], relk[0..3][110-d] }
//   g_relh[1][d] = { relv[0..7][d] }
__device__ __align__(16) __half g_relh[2][111][8];

__constant__ int   c_PA[10] = {0,0,0,0,1,1,1,2,2,3};
__constant__ int   c_PB[10] = {0,1,2,3,1,2,3,2,3,3};
__constant__ float c_PW[10] = {1.f,2.f,2.f,2.f,1.f,2.f,2.f,1.f,2.f,1.f};

// ---------------- K1: qkv = w @ x — split-channel, high-occupancy -----------
// grid = BTOT*2: block (b, half) computes 64 output channels.
// Side duties (consumed only by LATER kernels):
//   block 0:      zero g_osum/g_osq
//   blocks 0-13:  rel prefix tables (g_SR/g_TQ/g_TK)
//   blocks 14-27: fp16 rel tables (g_relh)
__global__ void __launch_bounds__(128) k_qkv(const float* __restrict__ x,
                                             const float* __restrict__ w,
                                             const float* __restrict__ relative) {
    __shared__ __align__(16) float xs[64][60];     // [c][i]
    __shared__ __align__(16) float wsT[64][66];    // [c][o_local]
    const int b = blockIdx.x >> 1;
    const int half = blockIdx.x & 1;
    const int obase = half * 64;
    const int t = threadIdx.x;

    if (blockIdx.x == 0 && t < 128) { g_osum[t] = 0.0; g_osq[t] = 0.0; }
    if (blockIdx.x < 14) {
        int task = blockIdx.x * 128 + t;
        if (task < 448) {
            int c = task / 56, i = task % 56;
            float s = 0.f;
            for (int d = 0; d < 56; ++d) s += relative[c * 111 + i + d];
            g_SR[c][i] = s;
        } else if (task < 1568) {
            int p = (task - 448) / 56, i = (task - 448) % 56;
            int pp = p % 10; int isK = (p >= 10) ? 4 : 0;
            int a = c_PA[pp] + isK, bb = c_PB[pp] + isK;
            float s = 0.f;
            for (int d = 0; d < 56; ++d)
                s += relative[a * 111 + i + d] * relative[bb * 111 + i + d];
            s *= c_PW[pp];
            if (isK) g_TK[pp][i] = s; else g_TQ[pp][i] = s;
        }
    } else if (blockIdx.x < 28) {
        int e = (blockIdx.x - 14) * 128 + t;
        if (e < 888) {
            int c = e & 7, d = e >> 3;
            g_relh[0][d][c] = __float2half(c < 4 ? relative[c * 111 + d]
                                                 : relative[c * 111 + 110 - d]);
        } else if (e < 1776) {
            int e2 = e - 888;
            int c = e2 & 7, d = e2 >> 3;
            g_relh[1][d][c] = __float2half(relative[(8 + c) * 111 + d]);
        }
    }

    for (int idx = t; idx < 64 * 14; idx += 128) {
        int c = idx / 14, q4 = idx % 14;
        *(float4*)&xs[c][q4 * 4] = *(const float4*)&x[c * XPLANE + b * 56 + q4 * 4];
    }
    for (int idx = t; idx < 64 * 64; idx += 128) {
        int ol = idx >> 6, c = idx & 63;
        wsT[c][ol] = w[(obase + ol) * 64 + c];
    }
    __syncthreads();

    const int og = t >> 3;                 // 0..15 (4 local channels each)
    const int ig = t & 7;                  // 0..7  (7 positions each)
    const int o0l = og * 4, i0 = ig * 7;
    u64t acc2[2][7];
#pragma unroll
    for (int p = 0; p < 2; ++p)
#pragma unroll
        for (int ii = 0; ii < 7; ++ii) acc2[p][ii] = 0ull;

    for (int c = 0; c < 64; ++c) {
        u64t w01 = *(const u64t*)&wsT[c][o0l];
        u64t w23 = *(const u64t*)&wsT[c][o0l + 2];
#pragma unroll
        for (int ii = 0; ii < 7; ++ii) {
            float xv = xs[c][i0 + ii];
            u64t xx = pack2(xv, xv);
            acc2[0][ii] = ffma2(w01, xx, acc2[0][ii]);
            acc2[1][ii] = ffma2(w23, xx, acc2[1][ii]);
        }
    }
    float* outb = g_qkv + (size_t)b * CH_STR + obase * 56;
#pragma unroll
    for (int p = 0; p < 2; ++p) {
        float s0 = 0.f, sq0 = 0.f, s1 = 0.f, sq1 = 0.f;
#pragma unroll
        for (int ii = 0; ii < 7; ++ii) {
            float2 u = unpack2(acc2[p][ii]);
            outb[(o0l + 2 * p) * 56 + i0 + ii]     = u.x;
            outb[(o0l + 2 * p + 1) * 56 + i0 + ii] = u.y;
            s0 += u.x; sq0 += u.x * u.x;
            s1 += u.y; sq1 += u.y * u.y;
        }
        for (int off = 4; off; off >>= 1) {
            s0  += __shfl_down_sync(0xffffffffu, s0,  off);
            sq0 += __shfl_down_sync(0xffffffffu, sq0, off);
            s1  += __shfl_down_sync(0xffffffffu, s1,  off);
            sq1 += __shfl_down_sync(0xffffffffu, sq1, off);
        }
        if (ig == 0) {
            atomicAdd(&g_qsum[obase + o0l + 2 * p],     (double)s0);
            atomicAdd(&g_qsq [obase + o0l + 2 * p],     (double)sq0);
            atomicAdd(&g_qsum[obase + o0l + 2 * p + 1], (double)s1);
            atomicAdd(&g_qsq [obase + o0l + 2 * p + 1], (double)sq1);
        }
    }
}

// ---------------- K2: analytic sim moments (folds qkv-BN finalize) ----------
__global__ void __launch_bounds__(256) k_mom(const float* __restrict__ qg,
                                             const float* __restrict__ qb) {
    __shared__ float sQs[128], sQo[128];
    const int b = blockIdx.x;
    {
        int o = threadIdx.x;
        if (o < 128) {
            double inv = 1.0 / NQKV;
            double m = g_qsum[o] * inv;
            double v = g_qsq[o] * inv - m * m;
            float sc = qg[o] * rsqrtf((float)v + EPSBN);
            sQs[o] = sc;
            sQo[o] = qb[o] - (float)m * sc;
        }
    }
    __syncthreads();

    const int g = threadIdx.x >> 5;
    const int lane = threadIdx.x & 31;
    const float* base = g_qkv + (size_t)b * CH_STR + g * 16 * 56;

    float part[32];
#pragma unroll
    for (int v = 0; v < 32; ++v) part[v] = 0.f;

#pragma unroll
    for (int ii = 0; ii < 2; ++ii) {
        int i = lane + ii * 32;
        if (i < 56) {
            float q[4], k[4];
#pragma unroll
            for (int c = 0; c < 4; ++c) {
                int oq = g * 16 + c, ok = g * 16 + 4 + c;
                q[c] = base[c * 56 + i]       * sQs[oq] + sQo[oq];
                k[c] = base[(4 + c) * 56 + i] * sQs[ok] + sQo[ok];
            }
#pragma unroll
            for (int c = 0; c < 4; ++c) {
                part[c]     += q[c];
                part[4 + c] += k[c];
                part[28] += q[c] * g_SR[c][i];
                part[30] += k[c] * g_SR[4 + c][i];
            }
#pragma unroll
            for (int p = 0; p < 10; ++p) {
                float pq = q[c_PA[p]] * q[c_PB[p]];
                float pk = k[c_PA[p]] * k[c_PB[p]];
                part[8 + p]  += pq;
                part[18 + p] += pk;
                part[29] += pq * g_TQ[p][i];
                part[31] += pk * g_TK[p][i];
            }
        }
    }
#pragma unroll
    for (int v = 0; v < 32; ++v)
        for (int off = 16; off; off >>= 1)
            part[v] += __shfl_down_sync(0xffffffffu, part[v], off);

    if (lane == 0) {
        float S1 = 0.f, S2 = 0.f;
#pragma unroll
        for (int c = 0; c < 4; ++c) S1 += part[c] * part[4 + c];
#pragma unroll
        for (int p = 0; p < 10; ++p) S2 += c_PW[p] * part[8 + p] * part[18 + p];
        atomicAdd(&g_ssum[g],      (double)S1);
        atomicAdd(&g_ssq [g],      (double)S2);
        atomicAdd(&g_ssum[8 + g],  (double)(0.1f  * part[28]));
        atomicAdd(&g_ssq [8 + g],  (double)(0.01f * part[29]));
        atomicAdd(&g_ssum[16 + g], (double)(0.1f  * part[30]));
        atomicAdd(&g_ssq [16 + g], (double)(0.01f * part[31]));
    }
}

// ---- warp reduce-scatter: 16 partials spread over 8 consecutive lanes ------
__device__ __forceinline__ void reduce_scatter16(const float* av, int tj,
                                                 float& o0, float& o1) {
    float a8[8];
#pragma unroll
    for (int v = 0; v < 8; ++v) {
        float snd = (tj & 1) ? av[v] : av[8 + v];
        float kp  = (tj & 1) ? av[8 + v] : av[v];
        a8[v] = kp + __shfl_xor_sync(0xffffffffu, snd, 1);
    }
    float a4[4];
#pragma unroll
    for (int v = 0; v < 4; ++v) {
        float snd = (tj & 2) ? a8[v] : a8[4 + v];
        float kp  = (tj & 2) ? a8[4 + v] : a8[v];
        a4[v] = kp + __shfl_xor_sync(0xffffffffu, snd, 2);
    }
    float a2[2];
#pragma unroll
    for (int v = 0; v < 2; ++v) {
        float snd = (tj & 4) ? a4[v] : a4[2 + v];
        float kp  = (tj & 4) ? a4[2 + v] : a4[v];
        a2[v] = kp + __shfl_xor_sync(0xffffffffu, snd, 4);
    }
    o0 = a2[0]; o1 = a2[1];
}

// ---------------- K3: attention — grid 3584 = (b, head-half), 4 heads -------
// Rel tables copied from precomputed fp16 globals (222 uint4 per block).
__global__ void __launch_bounds__(224, 5) k_attn(const float* __restrict__ qg,
                                                 const float* __restrict__ qb,
                                                 const float* __restrict__ sg,
                                                 const float* __restrict__ sb) {
    __shared__ __align__(16) float qsT[4][56][4];
    __shared__ __align__(16) float ksT[4][56][4];
    __shared__ __align__(16) float vsT[4][56][12];   // 48B stride, conflict-free
    __shared__ __align__(16) __half relH[2][111][8]; // [0]=relQK, [1]=relV
    __shared__ __align__(16) float SB[16][60];
    __shared__ float sQs[64], sQo[64], sC[16];

    const int b = blockIdx.x >> 1;
    const int half = blockIdx.x & 1;
    const int gbase = half * 4;
    const int t = threadIdx.x;

    if (t < 64) {
        int o = half * 64 + t;
        double inv = 1.0 / NQKV;
        double m = g_qsum[o] * inv;
        double v = g_qsq[o] * inv - m * m;
        float sc = qg[o] * rsqrtf((float)v + EPSBN);
        sQs[t] = sc;
        sQo[t] = qb[o] - (float)m * sc;
    } else if (t < 68) {
        int gl = t - 64;
        int g = gbase + gl;
        double inv = 1.0 / NSIM;
        float fac[3] = {1.f, 0.1f, 0.1f};
        float csum = 0.f;
        for (int r = 0; r < 3; ++r) {
            int idx = r * 8 + g;
            double m = g_ssum[idx] * inv;
            double v = g_ssq[idx] * inv - m * m;
            float aa = sg[idx] * rsqrtf((float)v + EPSBN);
            sC[4 * gl + r] = aa * fac[r];
            csum += sb[idx] - (float)m * aa;
        }
        sC[4 * gl + 3] = csum;
    }
    // ---- rel tables: straight vector copy from fp16 globals ----
    if (t < 222) {
        ((uint4*)relH)[t] = ((const uint4*)g_relh)[t];
    }
    __syncthreads();

    {
        const float* src = g_qkv + (size_t)b * CH_STR + half * 64 * 56;
        const int chr = t / 14, i4 = t % 14;
#pragma unroll
        for (int it = 0; it < 4; ++it) {
            int ch = it * 16 + chr;
            float4 v = *(const float4*)&src[ch * 56 + i4 * 4];
            float sc = sQs[ch], of = sQo[ch];
            float vals[4] = {v.x * sc + of, v.y * sc + of, v.z * sc + of, v.w * sc + of};
            int gl = it, cc = chr;
#pragma unroll
            for (int e = 0; e < 4; ++e) {
                int i = i4 * 4 + e;
                if (cc < 4) qsT[gl][i][cc] = vals[e];
                else if (cc < 8) ksT[gl][i][cc - 4] = vals[e];
                else vsT[gl][i][cc - 8] = vals[e];
            }
        }
    }
    __syncthreads();

    const int lane = t & 31;
    const int tj = lane & 7, ig = lane >> 3;
    const int ti = (t >> 5) * 4 + ig;
    const int i0 = ti * 2, j0 = tj * 7;
    const int dbase = i0 - j0 + 49;
    const int chown = ((tj & 1) << 2) | (tj & 2) | ((tj >> 2) & 1);
    const int row_w = t / 14, c4_w = t % 14;

#pragma unroll 1
    for (int gl = 0; gl < 4; ++gl) {
        const int g = gbase + gl;
        const float cqk = sC[4 * gl], cqr = sC[4 * gl + 1], ckr = sC[4 * gl + 2], soff = sC[4 * gl + 3];

        float4 q0v = *(const float4*)qsT[gl][i0];
        float4 q1v = *(const float4*)qsT[gl][i0 + 1];

        float P[14];
        {
            float4 kcur, kprev;
#pragma unroll
            for (int cc = 0; cc < 8; ++cc) {
                int d = dbase + cc;
                uint4 rw = *(const uint4*)relH[0][d];
                const __half2* hp = (const __half2*)&rw;
                float2 ra = __half22float2(hp[0]);
                float2 rb = __half22float2(hp[1]);
                float2 rc = __half22float2(hp[2]);
                float2 rd = __half22float2(hp[3]);
                if (cc <= 6) {
                    kcur = *(const float4*)ksT[gl][j0 + 6 - cc];
                    float qk = q0v.x * kcur.x + q0v.y * kcur.y + q0v.z * kcur.z + q0v.w * kcur.w;
                    float qr = q0v.x * ra.x + q0v.y * ra.y + q0v.z * rb.x + q0v.w * rb.y;
                    float kr = kcur.x * rc.x + kcur.y * rc.y + kcur.z * rd.x + kcur.w * rd.y;
                    P[6 - cc] = fmaf(cqk, qk, fmaf(cqr, qr, fmaf(ckr, kr, soff)));
                }
                if (cc >= 1) {
                    float qk = q1v.x * kprev.x + q1v.y * kprev.y + q1v.z * kprev.z + q1v.w * kprev.w;
                    float qr = q1v.x * ra.x + q1v.y * ra.y + q1v.z * rb.x + q1v.w * rb.y;
                    float kr = kprev.x * rc.x + kprev.y * rc.y + kprev.z * rd.x + kprev.w * rd.y;
                    P[7 + 7 - cc] = fmaf(cqk, qk, fmaf(cqr, qr, fmaf(ckr, kr, soff)));
                }
                kprev = kcur;
            }
        }

        float rinv0, rinv1;
        {
            float rs0 = 0.f, rs1 = 0.f;
#pragma unroll
            for (int jj = 0; jj < 7; ++jj) {
                float p0 = __expf(P[jj]);
                float p1 = __expf(P[7 + jj]);
                P[jj] = p0; P[7 + jj] = p1;
                rs0 += p0; rs1 += p1;
            }
#pragma unroll
            for (int m = 1; m < 8; m <<= 1) {
                rs0 += __shfl_xor_sync(0xffffffffu, rs0, m);
                rs1 += __shfl_xor_sync(0xffffffffu, rs1, m);
            }
            rinv0 = 1.0f / rs0;
            rinv1 = 1.0f / rs1;
        }

        {
            u64t av2[8];
#pragma unroll
            for (int v = 0; v < 8; ++v) av2[v] = 0ull;
#pragma unroll
            for (int jj = 0; jj < 7; ++jj) {
                const float* vr = &vsT[gl][j0 + jj][0];
                u64t v01 = *(const u64t*)&vr[0];
                u64t v23 = *(const u64t*)&vr[2];
                u64t v45 = *(const u64t*)&vr[4];
                u64t v67 = *(const u64t*)&vr[6];
                u64t pp0 = pack2(P[jj], P[jj]);
                u64t pp1 = pack2(P[7 + jj], P[7 + jj]);
                av2[0] = ffma2(pp0, v01, av2[0]);
                av2[1] = ffma2(pp1, v01, av2[1]);
                av2[2] = ffma2(pp0, v23, av2[2]);
                av2[3] = ffma2(pp1, v23, av2[3]);
                av2[4] = ffma2(pp0, v45, av2[4]);
                av2[5] = ffma2(pp1, v45, av2[5]);
                av2[6] = ffma2(pp0, v67, av2[6]);
                av2[7] = ffma2(pp1, v67, av2[7]);
            }
            float av[16];
#pragma unroll
            for (int cp = 0; cp < 4; ++cp) {
#pragma unroll
                for (int r = 0; r < 2; ++r) {
                    float2 u = unpack2(av2[cp * 2 + r]);
                    av[2 * (2 * cp) + r]     = u.x;
                    av[2 * (2 * cp + 1) + r] = u.y;
                }
            }
            float s0, s1;
            reduce_scatter16(av, tj, s0, s1);
            SB[2 * chown][i0]     = s0 * rinv0;
            SB[2 * chown][i0 + 1] = s1 * rinv1;
        }

        {
            float av[16];
#pragma unroll
            for (int v = 0; v < 16; ++v) av[v] = 0.f;
#pragma unroll
            for (int cc = 0; cc < 8; ++cc) {
                int d = dbase + cc;
                uint4 rw = *(const uint4*)relH[1][d];
                const __half2* hp = (const __half2*)&rw;
                float2 va = __half22float2(hp[0]);
                float2 vb = __half22float2(hp[1]);
                float2 vc = __half22float2(hp[2]);
                float2 vd = __half22float2(hp[3]);
                if (cc <= 6) {
                    float p = P[6 - cc];
                    av[0] += p * va.x; av[2]  += p * va.y; av[4]  += p * vb.x; av[6]  += p * vb.y;
                    av[8] += p * vc.x; av[10] += p * vc.y; av[12] += p * vd.x; av[14] += p * vd.y;
                }
                if (cc >= 1) {
                    float p = P[7 + 7 - cc];
                    av[1] += p * va.x; av[3]  += p * va.y; av[5]  += p * vb.x; av[7]  += p * vb.y;
                    av[9] += p * vc.x; av[11] += p * vc.y; av[13] += p * vd.x; av[15] += p * vd.y;
                }
            }
            float s0, s1;
            reduce_scatter16(av, tj, s0, s1);
            SB[2 * chown + 1][i0]     = s0 * rinv0 * 0.1f;
            SB[2 * chown + 1][i0 + 1] = s1 * rinv1 * 0.1f;
        }
        __syncthreads();

        {
            float4 v4 = *(const float4*)&SB[row_w][c4_w * 4];
            __half2 h0 = __floats2half2_rn(v4.x, v4.y);
            __half2 h1 = __floats2half2_rn(v4.z, v4.w);
            __half* ob = g_so + (size_t)b * CH_STR + g * 16 * 56 + row_w * 56 + c4_w * 4;
            uint2 st;
            st.x = *(unsigned*)&h0;
            st.y = *(unsigned*)&h1;
            *(uint2*)ob = st;
        }

        if (t < 128) {
            int row = t >> 3, sub = t & 7;
            float s1 = 0.f, s2 = 0.f;
#pragma unroll
            for (int e = 0; e < 7; ++e) {
                float v = SB[row][sub * 7 + e];
                s1 += v; s2 += v * v;
            }
#pragma unroll
            for (int m = 1; m < 8; m <<= 1) {
                s1 += __shfl_xor_sync(0xffffffffu, s1, m);
                s2 += __shfl_xor_sync(0xffffffffu, s2, m);
            }
            if (sub == 0) {
                atomicAdd(&g_osum[g * 16 + row], (double)s1);
                atomicAdd(&g_osq [g * 16 + row], (double)s2);
            }
        }
        __syncthreads();
    }
}

// ---------------- K4: out BN + pair-sum + layout; 2 chunks/thread -----------
__global__ void __launch_bounds__(256) k_out(float* __restrict__ out,
                                             const float* __restrict__ og,
                                             const float* __restrict__ ob) {
    __shared__ float sOs[128], sOo[128];
    {
        int o = threadIdx.x;
        if (o < 128) {
            double inv = 1.0 / NQKV;
            double m = g_osum[o] * inv;
            double v = g_osq[o] * inv - m * m;
            float sc = og[o] * rsqrtf((float)v + EPSBN);
            sOs[o] = sc;
            sOo[o] = ob[o] - (float)m * sc;
        }
    }
    if (blockIdx.x == 0) {
        int o = threadIdx.x;
        if (o < 128) { g_qsum[o] = 0.0; g_qsq[o] = 0.0; }
        if (o >= 128 && o < 152) { g_ssum[o - 128] = 0.0; g_ssq[o - 128] = 0.0; }
    }
    __syncthreads();
    int idx0 = blockIdx.x * 256 + threadIdx.x;
#pragma unroll
    for (int rpt = 0; rpt < 2; ++rpt) {
        int idx = idx0 + rpt * 802816;          // 3136*256 = 802816; total 1605632
        int e  = idx * 4;
        int cp = e / XPLANE;
        int r  = e % XPLANE;
        int bq = r / 56, i = r % 56;
        const __half* base = g_so + (size_t)bq * CH_STR + (2 * cp) * 56 + i;
        uint2 a = *(const uint2*)base;
        uint2 bb = *(const uint2*)(base + 56);
        __half2 ha0, ha1, hb0, hb1;
        *(unsigned*)&ha0 = a.x;  *(unsigned*)&ha1 = a.y;
        *(unsigned*)&hb0 = bb.x; *(unsigned*)&hb1 = bb.y;
        float2 s0a = __half22float2(ha0), s0b = __half22float2(ha1);
        float2 s1a = __half22float2(hb0), s1b = __half22float2(hb1);
        float sc0 = sOs[2 * cp], of0 = sOo[2 * cp];
        float sc1 = sOs[2 * cp + 1], of1 = sOo[2 * cp + 1];
        float4 o4;
        o4.x = s0a.x * sc0 + of0 + s1a.x * sc1 + of1;
        o4.y = s0a.y * sc0 + of0 + s1a.y * sc1 + of1;
        o4.z = s0b.x * sc0 + of0 + s1b.x * sc1 + of1;
        o4.w = s0b.y * sc0 + of0 + s1b.y * sc1 + of1;
        *(float4*)&out[e] = o4;
    }
}

// ---------------- launch -----------------------------------------------------
extern "C" void kernel_launch(void* const* d_in, const int* in_sizes, int n_in,
                              void* d_out, int out_size) {
    const float* x        = (const float*)d_in[0];
    const float* w_qkv    = (const float*)d_in[1];
    const float* relative = (const float*)d_in[2];
    const float* qg       = (const float*)d_in[3];
    const float* qb       = (const float*)d_in[4];
    const float* sg       = (const float*)d_in[5];
    const float* sb       = (const float*)d_in[6];
    const float* og       = (const float*)d_in[7];
    const float* ob       = (const float*)d_in[8];
    float* out            = (float*)d_out;

    k_qkv  <<<BTOT * 2, 128>>>(x, w_qkv, relative);
    k_mom  <<<BTOT, 256>>>(qg, qb);
    k_attn <<<BTOT * 2, 224>>>(qg, qb, sg, sb);
    k_out  <<<3136, 256>>>(out, og, ob);
}

// round 17
// speedup vs baseline: 1.2177x; 1.0005x over previous
#include <cuda_runtime.h>
#include <cuda_fp16.h>
#include <math.h>

// Problem constants
#define BTOT   1792          // N*D*H = 1*32*56
#define CH_STR 7168          // 128*56
#define XPLANE 100352        // 32*56*56 == BTOT*56
#define NQKV   100352.0
#define NSIM   5619712.0     // BTOT*56*56
#define EPSBN  1e-5f
#define LOG2E  1.4426950408889634f

typedef unsigned long long u64t;

// ---- packed fp32x2 helpers (sm_103a dual-fp32; lanewise IEEE fp32) ---------
__device__ __forceinline__ u64t pack2(float lo, float hi) {
    u64t d; asm("mov.b64 %0, {%1, %2};" : "=l"(d) : "f"(lo), "f"(hi)); return d;
}
__device__ __forceinline__ float2 unpack2(u64t d) {
    float2 r; asm("mov.b64 {%0, %1}, %2;" : "=f"(r.x), "=f"(r.y) : "l"(d)); return r;
}
__device__ __forceinline__ u64t ffma2(u64t a, u64t b, u64t c) {
    u64t d; asm("fma.rn.f32x2 %0, %1, %2, %3;" : "=l"(d) : "l"(a), "l"(b), "l"(c));
    return d;
}
__device__ __forceinline__ float ex2f(float x) {
    float r; asm("ex2.approx.f32 %0, %1;" : "=f"(r) : "f"(x)); return r;
}

// ---------------- scratch (device globals; no runtime alloc) ----------------
__device__ float  g_qkv[BTOT * 128 * 56];  // [b][o][i]  o = g*16+cc
__device__ __half g_so [BTOT * 128 * 56];  // [b][o2][i] fp16 (stats kept fp32)
__device__ double g_qsum[128], g_qsq[128]; // zeroed by k_out (prev invocation)
__device__ double g_ssum[24],  g_ssq[24];  // zeroed by k_out (prev invocation)
__device__ double g_osum[128], g_osq[128]; // zeroed by k_qkv block 0
__device__ float g_SR[8][56];
__device__ float g_TQ[10][56];
__device__ float g_TK[10][56];
// fp16 rel tables, precomputed by k_qkv side blocks:
//   g_relh[0][d] = { relq[0..3][d], relk[0..3][110-d] }
//   g_relh[1][d] = { relv[0..7][d] }
__device__ __align__(16) __half g_relh[2][111][8];

__constant__ int   c_PA[10] = {0,0,0,0,1,1,1,2,2,3};
__constant__ int   c_PB[10] = {0,1,2,3,1,2,3,2,3,3};
__constant__ float c_PW[10] = {1.f,2.f,2.f,2.f,1.f,2.f,2.f,1.f,2.f,1.f};

// ---------------- K1: qkv = w @ x — split-channel, high-occupancy -----------
// grid = BTOT*2: block (b, half) computes 64 output channels.
// Side duties (consumed only by LATER kernels):
//   block 0:      zero g_osum/g_osq
//   blocks 0-13:  rel prefix tables (g_SR/g_TQ/g_TK)
//   blocks 14-27: fp16 rel tables (g_relh)
__global__ void __launch_bounds__(128) k_qkv(const float* __restrict__ x,
                                             const float* __restrict__ w,
                                             const float* __restrict__ relative) {
    __shared__ __align__(16) float xs[64][60];     // [c][i]
    __shared__ __align__(16) float wsT[64][66];    // [c][o_local]
    const int b = blockIdx.x >> 1;
    const int half = blockIdx.x & 1;
    const int obase = half * 64;
    const int t = threadIdx.x;

    if (blockIdx.x == 0 && t < 128) { g_osum[t] = 0.0; g_osq[t] = 0.0; }
    if (blockIdx.x < 14) {
        int task = blockIdx.x * 128 + t;
        if (task < 448) {
            int c = task / 56, i = task % 56;
            float s = 0.f;
            for (int d = 0; d < 56; ++d) s += relative[c * 111 + i + d];
            g_SR[c][i] = s;
        } else if (task < 1568) {
            int p = (task - 448) / 56, i = (task - 448) % 56;
            int pp = p % 10; int isK = (p >= 10) ? 4 : 0;
            int a = c_PA[pp] + isK, bb = c_PB[pp] + isK;
            float s = 0.f;
            for (int d = 0; d < 56; ++d)
                s += relative[a * 111 + i + d] * relative[bb * 111 + i + d];
            s *= c_PW[pp];
            if (isK) g_TK[pp][i] = s; else g_TQ[pp][i] = s;
        }
    } else if (blockIdx.x < 28) {
        int e = (blockIdx.x - 14) * 128 + t;
        if (e < 888) {
            int c = e & 7, d = e >> 3;
            g_relh[0][d][c] = __float2half(c < 4 ? relative[c * 111 + d]
                                                 : relative[c * 111 + 110 - d]);
        } else if (e < 1776) {
            int e2 = e - 888;
            int c = e2 & 7, d = e2 >> 3;
            g_relh[1][d][c] = __float2half(relative[(8 + c) * 111 + d]);
        }
    }

    for (int idx = t; idx < 64 * 14; idx += 128) {
        int c = idx / 14, q4 = idx % 14;
        *(float4*)&xs[c][q4 * 4] = *(const float4*)&x[c * XPLANE + b * 56 + q4 * 4];
    }
    for (int idx = t; idx < 64 * 64; idx += 128) {
        int ol = idx >> 6, c = idx & 63;
        wsT[c][ol] = w[(obase + ol) * 64 + c];
    }
    __syncthreads();

    const int og = t >> 3;                 // 0..15 (4 local channels each)
    const int ig = t & 7;                  // 0..7  (7 positions each)
    const int o0l = og * 4, i0 = ig * 7;
    u64t acc2[2][7];
#pragma unroll
    for (int p = 0; p < 2; ++p)
#pragma unroll
        for (int ii = 0; ii < 7; ++ii) acc2[p][ii] = 0ull;

    for (int c = 0; c < 64; ++c) {
        u64t w01 = *(const u64t*)&wsT[c][o0l];
        u64t w23 = *(const u64t*)&wsT[c][o0l + 2];
#pragma unroll
        for (int ii = 0; ii < 7; ++ii) {
            float xv = xs[c][i0 + ii];
            u64t xx = pack2(xv, xv);
            acc2[0][ii] = ffma2(w01, xx, acc2[0][ii]);
            acc2[1][ii] = ffma2(w23, xx, acc2[1][ii]);
        }
    }
    float* outb = g_qkv + (size_t)b * CH_STR + obase * 56;
#pragma unroll
    for (int p = 0; p < 2; ++p) {
        float s0 = 0.f, sq0 = 0.f, s1 = 0.f, sq1 = 0.f;
#pragma unroll
        for (int ii = 0; ii < 7; ++ii) {
            float2 u = unpack2(acc2[p][ii]);
            outb[(o0l + 2 * p) * 56 + i0 + ii]     = u.x;
            outb[(o0l + 2 * p + 1) * 56 + i0 + ii] = u.y;
            s0 += u.x; sq0 += u.x * u.x;
            s1 += u.y; sq1 += u.y * u.y;
        }
        for (int off = 4; off; off >>= 1) {
            s0  += __shfl_down_sync(0xffffffffu, s0,  off);
            sq0 += __shfl_down_sync(0xffffffffu, sq0, off);
            s1  += __shfl_down_sync(0xffffffffu, s1,  off);
            sq1 += __shfl_down_sync(0xffffffffu, sq1, off);
        }
        if (ig == 0) {
            atomicAdd(&g_qsum[obase + o0l + 2 * p],     (double)s0);
            atomicAdd(&g_qsq [obase + o0l + 2 * p],     (double)sq0);
            atomicAdd(&g_qsum[obase + o0l + 2 * p + 1], (double)s1);
            atomicAdd(&g_qsq [obase + o0l + 2 * p + 1], (double)sq1);
        }
    }
}

// ---------------- K2: analytic sim moments (folds qkv-BN finalize) ----------
__global__ void __launch_bounds__(256) k_mom(const float* __restrict__ qg,
                                             const float* __restrict__ qb) {
    __shared__ float sQs[128], sQo[128];
    const int b = blockIdx.x;
    {
        int o = threadIdx.x;
        if (o < 128) {
            double inv = 1.0 / NQKV;
            double m = g_qsum[o] * inv;
            double v = g_qsq[o] * inv - m * m;
            float sc = qg[o] * rsqrtf((float)v + EPSBN);
            sQs[o] = sc;
            sQo[o] = qb[o] - (float)m * sc;
        }
    }
    __syncthreads();

    const int g = threadIdx.x >> 5;
    const int lane = threadIdx.x & 31;
    const float* base = g_qkv + (size_t)b * CH_STR + g * 16 * 56;

    float part[32];
#pragma unroll
    for (int v = 0; v < 32; ++v) part[v] = 0.f;

#pragma unroll
    for (int ii = 0; ii < 2; ++ii) {
        int i = lane + ii * 32;
        if (i < 56) {
            float q[4], k[4];
#pragma unroll
            for (int c = 0; c < 4; ++c) {
                int oq = g * 16 + c, ok = g * 16 + 4 + c;
                q[c] = base[c * 56 + i]       * sQs[oq] + sQo[oq];
                k[c] = base[(4 + c) * 56 + i] * sQs[ok] + sQo[ok];
            }
#pragma unroll
            for (int c = 0; c < 4; ++c) {
                part[c]     += q[c];
                part[4 + c] += k[c];
                part[28] += q[c] * g_SR[c][i];
                part[30] += k[c] * g_SR[4 + c][i];
            }
#pragma unroll
            for (int p = 0; p < 10; ++p) {
                float pq = q[c_PA[p]] * q[c_PB[p]];
                float pk = k[c_PA[p]] * k[c_PB[p]];
                part[8 + p]  += pq;
                part[18 + p] += pk;
                part[29] += pq * g_TQ[p][i];
                part[31] += pk * g_TK[p][i];
            }
        }
    }
#pragma unroll
    for (int v = 0; v < 32; ++v)
        for (int off = 16; off; off >>= 1)
            part[v] += __shfl_down_sync(0xffffffffu, part[v], off);

    if (lane == 0) {
        float S1 = 0.f, S2 = 0.f;
#pragma unroll
        for (int c = 0; c < 4; ++c) S1 += part[c] * part[4 + c];
#pragma unroll
        for (int p = 0; p < 10; ++p) S2 += c_PW[p] * part[8 + p] * part[18 + p];
        atomicAdd(&g_ssum[g],      (double)S1);
        atomicAdd(&g_ssq [g],      (double)S2);
        atomicAdd(&g_ssum[8 + g],  (double)(0.1f  * part[28]));
        atomicAdd(&g_ssq [8 + g],  (double)(0.01f * part[29]));
        atomicAdd(&g_ssum[16 + g], (double)(0.1f  * part[30]));
        atomicAdd(&g_ssq [16 + g], (double)(0.01f * part[31]));
    }
}

// ---- warp reduce-scatter: 16 partials spread over 8 consecutive lanes ------
__device__ __forceinline__ void reduce_scatter16(const float* av, int tj,
                                                 float& o0, float& o1) {
    float a8[8];
#pragma unroll
    for (int v = 0; v < 8; ++v) {
        float snd = (tj & 1) ? av[v] : av[8 + v];
        float kp  = (tj & 1) ? av[8 + v] : av[v];
        a8[v] = kp + __shfl_xor_sync(0xffffffffu, snd, 1);
    }
    float a4[4];
#pragma unroll
    for (int v = 0; v < 4; ++v) {
        float snd = (tj & 2) ? a8[v] : a8[4 + v];
        float kp  = (tj & 2) ? a8[4 + v] : a8[v];
        a4[v] = kp + __shfl_xor_sync(0xffffffffu, snd, 2);
    }
    float a2[2];
#pragma unroll
    for (int v = 0; v < 2; ++v) {
        float snd = (tj & 4) ? a4[v] : a4[2 + v];
        float kp  = (tj & 4) ? a4[2 + v] : a4[v];
        a2[v] = kp + __shfl_xor_sync(0xffffffffu, snd, 4);
    }
    o0 = a2[0]; o1 = a2[1];
}

// ---------------- K3: attention — grid 3584, double-buffered SB, ex2 --------
__global__ void __launch_bounds__(224, 5) k_attn(const float* __restrict__ qg,
                                                 const float* __restrict__ qb,
                                                 const float* __restrict__ sg,
                                                 const float* __restrict__ sb) {
    __shared__ __align__(16) float qsT[4][56][4];
    __shared__ __align__(16) float ksT[4][56][4];
    __shared__ __align__(16) float vsT[4][56][12];   // 48B stride, conflict-free
    __shared__ __align__(16) __half relH[2][111][8]; // [0]=relQK, [1]=relV
    __shared__ __align__(16) float SB[2][16][60];    // double-buffered
    __shared__ float sQs[64], sQo[64], sC[16];

    const int b = blockIdx.x >> 1;
    const int half = blockIdx.x & 1;
    const int gbase = half * 4;
    const int t = threadIdx.x;

    if (t < 64) {
        int o = half * 64 + t;
        double inv = 1.0 / NQKV;
        double m = g_qsum[o] * inv;
        double v = g_qsq[o] * inv - m * m;
        float sc = qg[o] * rsqrtf((float)v + EPSBN);
        sQs[t] = sc;
        sQo[t] = qb[o] - (float)m * sc;
    } else if (t < 68) {
        int gl = t - 64;
        int g = gbase + gl;
        double inv = 1.0 / NSIM;
        float fac[3] = {1.f, 0.1f, 0.1f};
        float csum = 0.f;
        for (int r = 0; r < 3; ++r) {
            int idx = r * 8 + g;
            double m = g_ssum[idx] * inv;
            double v = g_ssq[idx] * inv - m * m;
            float aa = sg[idx] * rsqrtf((float)v + EPSBN);
            sC[4 * gl + r] = aa * fac[r] * LOG2E;   // fold log2(e) for ex2
            csum += sb[idx] - (float)m * aa;
        }
        sC[4 * gl + 3] = csum * LOG2E;
    }
    // ---- rel tables: straight vector copy from fp16 globals ----
    if (t < 222) {
        ((uint4*)relH)[t] = ((const uint4*)g_relh)[t];
    }
    __syncthreads();

    {
        const float* src = g_qkv + (size_t)b * CH_STR + half * 64 * 56;
        const int chr = t / 14, i4 = t % 14;
#pragma unroll
        for (int it = 0; it < 4; ++it) {
            int ch = it * 16 + chr;
            float4 v = *(const float4*)&src[ch * 56 + i4 * 4];
            float sc = sQs[ch], of = sQo[ch];
            float vals[4] = {v.x * sc + of, v.y * sc + of, v.z * sc + of, v.w * sc + of};
            int gl = it, cc = chr;
#pragma unroll
            for (int e = 0; e < 4; ++e) {
                int i = i4 * 4 + e;
                if (cc < 4) qsT[gl][i][cc] = vals[e];
                else if (cc < 8) ksT[gl][i][cc - 4] = vals[e];
                else vsT[gl][i][cc - 8] = vals[e];
            }
        }
    }
    __syncthreads();

    const int lane = t & 31;
    const int tj = lane & 7, ig = lane >> 3;
    const int ti = (t >> 5) * 4 + ig;
    const int i0 = ti * 2, j0 = tj * 7;
    const int dbase = i0 - j0 + 49;
    const int chown = ((tj & 1) << 2) | (tj & 2) | ((tj >> 2) & 1);
    const int row_w = t / 14, c4_w = t % 14;

#pragma unroll 1
    for (int gl = 0; gl < 4; ++gl) {
        const int g = gbase + gl;
        const int sbuf = gl & 1;
        const float cqk = sC[4 * gl], cqr = sC[4 * gl + 1], ckr = sC[4 * gl + 2], soff = sC[4 * gl + 3];

        float4 q0v = *(const float4*)qsT[gl][i0];
        float4 q1v = *(const float4*)qsT[gl][i0 + 1];

        float P[14];
        {
            float4 kcur, kprev;
#pragma unroll
            for (int cc = 0; cc < 8; ++cc) {
                int d = dbase + cc;
                uint4 rw = *(const uint4*)relH[0][d];
                const __half2* hp = (const __half2*)&rw;
                float2 ra = __half22float2(hp[0]);
                float2 rb = __half22float2(hp[1]);
                float2 rc = __half22float2(hp[2]);
                float2 rd = __half22float2(hp[3]);
                if (cc <= 6) {
                    kcur = *(const float4*)ksT[gl][j0 + 6 - cc];
                    float qk = q0v.x * kcur.x + q0v.y * kcur.y + q0v.z * kcur.z + q0v.w * kcur.w;
                    float qr = q0v.x * ra.x + q0v.y * ra.y + q0v.z * rb.x + q0v.w * rb.y;
                    float kr = kcur.x * rc.x + kcur.y * rc.y + kcur.z * rd.x + kcur.w * rd.y;
                    P[6 - cc] = fmaf(cqk, qk, fmaf(cqr, qr, fmaf(ckr, kr, soff)));
                }
                if (cc >= 1) {
                    float qk = q1v.x * kprev.x + q1v.y * kprev.y + q1v.z * kprev.z + q1v.w * kprev.w;
                    float qr = q1v.x * ra.x + q1v.y * ra.y + q1v.z * rb.x + q1v.w * rb.y;
                    float kr = kprev.x * rc.x + kprev.y * rc.y + kprev.z * rd.x + kprev.w * rd.y;
                    P[7 + 7 - cc] = fmaf(cqk, qk, fmaf(cqr, qr, fmaf(ckr, kr, soff)));
                }
                kprev = kcur;
            }
        }

        float rinv0, rinv1;
        {
            float rs0 = 0.f, rs1 = 0.f;
#pragma unroll
            for (int jj = 0; jj < 7; ++jj) {
                float p0 = ex2f(P[jj]);         // logits pre-scaled by log2e
                float p1 = ex2f(P[7 + jj]);
                P[jj] = p0; P[7 + jj] = p1;
                rs0 += p0; rs1 += p1;
            }
#pragma unroll
            for (int m = 1; m < 8; m <<= 1) {
                rs0 += __shfl_xor_sync(0xffffffffu, rs0, m);
                rs1 += __shfl_xor_sync(0xffffffffu, rs1, m);
            }
            rinv0 = 1.0f / rs0;
            rinv1 = 1.0f / rs1;
        }

        {
            u64t av2[8];
#pragma unroll
            for (int v = 0; v < 8; ++v) av2[v] = 0ull;
#pragma unroll
            for (int jj = 0; jj < 7; ++jj) {
                const float* vr = &vsT[gl][j0 + jj][0];
                u64t v01 = *(const u64t*)&vr[0];
                u64t v23 = *(const u64t*)&vr[2];
                u64t v45 = *(const u64t*)&vr[4];
                u64t v67 = *(const u64t*)&vr[6];
                u64t pp0 = pack2(P[jj], P[jj]);
                u64t pp1 = pack2(P[7 + jj], P[7 + jj]);
                av2[0] = ffma2(pp0, v01, av2[0]);
                av2[1] = ffma2(pp1, v01, av2[1]);
                av2[2] = ffma2(pp0, v23, av2[2]);
                av2[3] = ffma2(pp1, v23, av2[3]);
                av2[4] = ffma2(pp0, v45, av2[4]);
                av2[5] = ffma2(pp1, v45, av2[5]);
                av2[6] = ffma2(pp0, v67, av2[6]);
                av2[7] = ffma2(pp1, v67, av2[7]);
            }
            float av[16];
#pragma unroll
            for (int cp = 0; cp < 4; ++cp) {
#pragma unroll
                for (int r = 0; r < 2; ++r) {
                    float2 u = unpack2(av2[cp * 2 + r]);
                    av[2 * (2 * cp) + r]     = u.x;
                    av[2 * (2 * cp + 1) + r] = u.y;
                }
            }
            float s0, s1;
            reduce_scatter16(av, tj, s0, s1);
            SB[sbuf][2 * chown][i0]     = s0 * rinv0;
            SB[sbuf][2 * chown][i0 + 1] = s1 * rinv1;
        }

        {
            float av[16];
#pragma unroll
            for (int v = 0; v < 16; ++v) av[v] = 0.f;
#pragma unroll
            for (int cc = 0; cc < 8; ++cc) {
                int d = dbase + cc;
                uint4 rw = *(const uint4*)relH[1][d];
                const __half2* hp = (const __half2*)&rw;
                float2 va = __half22float2(hp[0]);
                float2 vb = __half22float2(hp[1]);
                float2 vc = __half22float2(hp[2]);
                float2 vd = __half22float2(hp[3]);
                if (cc <= 6) {
                    float p = P[6 - cc];
                    av[0] += p * va.x; av[2]  += p * va.y; av[4]  += p * vb.x; av[6]  += p * vb.y;
                    av[8] += p * vc.x; av[10] += p * vc.y; av[12] += p * vd.x; av[14] += p * vd.y;
                }
                if (cc >= 1) {
                    float p = P[7 + 7 - cc];
                    av[1] += p * va.x; av[3]  += p * va.y; av[5]  += p * vb.x; av[7]  += p * vb.y;
                    av[9] += p * vc.x; av[11] += p * vc.y; av[13] += p * vd.x; av[15] += p * vd.y;
                }
            }
            float s0, s1;
            reduce_scatter16(av, tj, s0, s1);
            SB[sbuf][2 * chown + 1][i0]     = s0 * rinv0 * 0.1f;
            SB[sbuf][2 * chown + 1][i0 + 1] = s1 * rinv1 * 0.1f;
        }
        __syncthreads();      // single sync: orders prev consumers + this write

        {
            float4 v4 = *(const float4*)&SB[sbuf][row_w][c4_w * 4];
            __half2 h0 = __floats2half2_rn(v4.x, v4.y);
            __half2 h1 = __floats2half2_rn(v4.z, v4.w);
            __half* ob = g_so + (size_t)b * CH_STR + g * 16 * 56 + row_w * 56 + c4_w * 4;
            uint2 st;
            st.x = *(unsigned*)&h0;
            st.y = *(unsigned*)&h1;
            *(uint2*)ob = st;
        }

        if (t < 128) {
            int row = t >> 3, sub = t & 7;
            float s1 = 0.f, s2 = 0.f;
#pragma unroll
            for (int e = 0; e < 7; ++e) {
                float v = SB[sbuf][row][sub * 7 + e];
                s1 += v; s2 += v * v;
            }
#pragma unroll
            for (int m = 1; m < 8; m <<= 1) {
                s1 += __shfl_xor_sync(0xffffffffu, s1, m);
                s2 += __shfl_xor_sync(0xffffffffu, s2, m);
            }
            if (sub == 0) {
                atomicAdd(&g_osum[g * 16 + row], (double)s1);
                atomicAdd(&g_osq [g * 16 + row], (double)s2);
            }
        }
        // no trailing sync: next iter writes the OTHER SB buffer; its single
        // sync orders these consumers before any reuse of this buffer.
    }
}

// ---------------- K4: out BN + pair-sum + layout; 4 chunks/thread -----------
__global__ void __launch_bounds__(256) k_out(float* __restrict__ out,
                                             const float* __restrict__ og,
                                             const float* __restrict__ ob) {
    __shared__ float sOs[128], sOo[128];
    {
        int o = threadIdx.x;
        if (o < 128) {
            double inv = 1.0 / NQKV;
            double m = g_osum[o] * inv;
            double v = g_osq[o] * inv - m * m;
            float sc = og[o] * rsqrtf((float)v + EPSBN);
            sOs[o] = sc;
            sOo[o] = ob[o] - (float)m * sc;
        }
    }
    if (blockIdx.x == 0) {
        int o = threadIdx.x;
        if (o < 128) { g_qsum[o] = 0.0; g_qsq[o] = 0.0; }
        if (o >= 128 && o < 152) { g_ssum[o - 128] = 0.0; g_ssq[o - 128] = 0.0; }
    }
    __syncthreads();
    int idx0 = blockIdx.x * 256 + threadIdx.x;
#pragma unroll
    for (int rpt = 0; rpt < 4; ++rpt) {
        int idx = idx0 + rpt * 401408;          // 1568*256 = 401408; 4x = 1605632
        int e  = idx * 4;
        int cp = e / XPLANE;
        int r  = e % XPLANE;
        int bq = r / 56, i = r % 56;
        const __half* base = g_so + (size_t)bq * CH_STR + (2 * cp) * 56 + i;
        uint2 a = *(const uint2*)base;
        uint2 bb = *(const uint2*)(base + 56);
        __half2 ha0, ha1, hb0, hb1;
        *(unsigned*)&ha0 = a.x;  *(unsigned*)&ha1 = a.y;
        *(unsigned*)&hb0 = bb.x; *(unsigned*)&hb1 = bb.y;
        float2 s0a = __half22float2(ha0), s0b = __half22float2(ha1);
        float2 s1a = __half22float2(hb0), s1b = __half22float2(hb1);
        float sc0 = sOs[2 * cp], of0 = sOo[2 * cp];
        float sc1 = sOs[2 * cp + 1], of1 = sOo[2 * cp + 1];
        float4 o4;
        o4.x = s0a.x * sc0 + of0 + s1a.x * sc1 + of1;
        o4.y = s0a.y * sc0 + of0 + s1a.y * sc1 + of1;
        o4.z = s0b.x * sc0 + of0 + s1b.x * sc1 + of1;
        o4.w = s0b.y * sc0 + of0 + s1b.y * sc1 + of1;
        *(float4*)&out[e] = o4;
    }
}

// ---------------- launch -----------------------------------------------------
extern "C" void kernel_launch(void* const* d_in, const int* in_sizes, int n_in,
                              void* d_out, int out_size) {
    const float* x        = (const float*)d_in[0];
    const float* w_qkv    = (const float*)d_in[1];
    const float* relative = (const float*)d_in[2];
    const float* qg       = (const float*)d_in[3];
    const float* qb       = (const float*)d_in[4];
    const float* sg       = (const float*)d_in[5];
    const float* sb       = (const float*)d_in[6];
    const float* og       = (const float*)d_in[7];
    const float* ob       = (const float*)d_in[8];
    float* out            = (float*)d_out;

    k_qkv  <<<BTOT * 2, 128>>>(x, w_qkv, relative);
    k_mom  <<<BTOT, 256>>>(qg, qb);
    k_attn <<<BTOT * 2, 224>>>(qg, qb, sg, sb);
    k_out  <<<1568, 256>>>(out, og, ob);
}